// round 11
// baseline (speedup 1.0000x reference)
#include <cuda_runtime.h>
#include <cuda_fp16.h>
#include <cstdint>

#define N_ROWS 524288
#define DIM 256
#define NSEG 8192
#define M_TILES 4096      // 128-row M tiles
#define GRID_A 148

// ---------------- scratch (device globals) ----------------------------------
__device__ float    g_seg_sum[NSEG * DIM];
__device__ unsigned g_seg_max[NSEG * DIM];
__device__ int      g_rowstart[NSEG + 1];
__device__ __half   g_W1h[DIM * DIM];
__device__ __half   g_Wph[DIM * 2 * DIM];
__device__ __half   g_xh[(size_t)N_ROWS * DIM];   // 268 MB fp16 copy of x

// ---------------- helpers ----------------------------------------------------
__device__ __forceinline__ uint32_t smem_u32(const void* p) {
    uint32_t a;
    asm("{ .reg .u64 t; cvta.to.shared.u64 t, %1; cvt.u32.u64 %0, t; }" : "=r"(a) : "l"(p));
    return a;
}
__device__ __forceinline__ void ldmat_x4(uint32_t r[4], uint32_t addr) {
    asm volatile("ldmatrix.sync.aligned.m8n8.x4.shared.b16 {%0,%1,%2,%3}, [%4];"
                 : "=r"(r[0]), "=r"(r[1]), "=r"(r[2]), "=r"(r[3]) : "r"(addr));
}
__device__ __forceinline__ void mma16816(float d[4], const uint32_t a[4],
                                         uint32_t b0, uint32_t b1) {
    asm volatile("mma.sync.aligned.m16n8k16.row.col.f32.f16.f16.f32 "
                 "{%0,%1,%2,%3}, {%4,%5,%6,%7}, {%8,%9}, {%0,%1,%2,%3};"
                 : "+f"(d[0]), "+f"(d[1]), "+f"(d[2]), "+f"(d[3])
                 : "r"(a[0]), "r"(a[1]), "r"(a[2]), "r"(a[3]), "r"(b0), "r"(b1));
}
__device__ __forceinline__ void sts8(uint32_t addr, uint32_t u0, uint32_t u1) {
    asm volatile("st.shared.v2.b32 [%0], {%1,%2};" :: "r"(addr), "r"(u0), "r"(u1) : "memory");
}
__device__ __forceinline__ void sts16(uint32_t addr, uint4 v) {
    asm volatile("st.shared.v4.b32 [%0], {%1,%2,%3,%4};"
                 :: "r"(addr), "r"(v.x), "r"(v.y), "r"(v.z), "r"(v.w) : "memory");
}
__device__ __forceinline__ void cpasync16(uint32_t dst, const void* src) {
    asm volatile("cp.async.cg.shared.global [%0], [%1], 16;" :: "r"(dst), "l"(src) : "memory");
}
#define CP_COMMIT() asm volatile("cp.async.commit_group;" ::: "memory")
#define CP_WAIT0()  asm volatile("cp.async.wait_group 0;"  ::: "memory")

__device__ __forceinline__ unsigned enc_f(float f) {
    unsigned i = __float_as_uint(f);
    return (i & 0x80000000u) ? ~i : (i | 0x80000000u);
}
__device__ __forceinline__ float dec_f(unsigned u) {
    return __uint_as_float((u & 0x80000000u) ? (u & 0x7FFFFFFFu) : ~u);
}
#define RSWZ(row) (((uint32_t)((row) & 7)) << 4)

// ---------------- kernel A smem layout (512B rows, swizzled) ----------------
#define OFF_W    0u          // 256 rows x 512B = 131072
#define OFF_A    131072u     // 128 rows x 512B = 65536
#define OFF_BIAS 196608u     // 1024
#define OFF_SEG  197632u     // 512
#define SMEM_A_BYTES 198144

// ---------------- proj smem layout (tile M=32) --------------------------------
#define P_OFF_B    0u        // Wp chunk: 256 x 128B = 32768
#define P_OFF_XA   32768u    // xpool chunk: 32 x 128B = 4096
#define P_OFF_OUT  36864u    // 32 x 260 x 4 = 33280
#define P_OFF_CNT  70144u    // 128
#define P_OFF_INV  70272u    // 128
#define P_OFF_BP   70400u    // 1024
#define SMEM_P_BYTES 71424
#define OUT_LD 260

// ---------------- prep: xconv (all blocks) + init/wconv/rowstart (role blocks)
__global__ void prep_kernel(const float* __restrict__ x,
                            const float* __restrict__ W1,
                            const float* __restrict__ Wp,
                            const int*   __restrict__ bidx)
{
    const int b = blockIdx.x;
    const int t = threadIdx.x;

    {
        const float4* x4 = (const float4*)x;
        uint2* o = (uint2*)g_xh;
        int base = b * 1024 + t;
#pragma unroll
        for (int i = 0; i < 4; i++) {
            float4 v = x4[base + i * 256];
            __half2 h0 = __floats2half2_rn(v.x, v.y);
            __half2 h1 = __floats2half2_rn(v.z, v.w);
            o[base + i * 256] = make_uint2(*(uint32_t*)&h0, *(uint32_t*)&h1);
        }
    }

    if (b < 8192) {                       // init
        int i = b * 256 + t;
        g_seg_sum[i] = 0.0f;
        g_seg_max[i] = 0u;
    } else if (b < 8192 + 384) {          // wconv
        int i = (b - 8192) * 256 + t;
        if (i < 32768) {
            float2 f = ((const float2*)W1)[i];
            ((__half2*)g_W1h)[i] = __floats2half2_rn(f.x, f.y);
        } else {
            int j = i - 32768;
            float2 f = ((const float2*)Wp)[j];
            ((__half2*)g_Wph)[j] = __floats2half2_rn(f.x, f.y);
        }
    } else if (b < 8192 + 384 + 32) {     // rowstart
        int s = (b - 8192 - 384) * 256 + t;
        int lo = 0, hi = N_ROWS;
        while (lo < hi) {
            int mid = (lo + hi) >> 1;
            if (__ldg(&bidx[mid]) < s) lo = mid + 1; else hi = mid;
        }
        g_rowstart[s] = lo;
        if (s == 0) g_rowstart[NSEG] = N_ROWS;
    }
}

// ---------------- kernel A: HMMA GEMM + shuffle segmented reduce -------------
// 256 thr = 8 warps (2M x 4N); warp tile 64x64; frag double-buffered mainloop.
__global__ void __launch_bounds__(256, 1) gemm_pool_mma(
    const int*   __restrict__ bidx,
    const float* __restrict__ b1)
{
    extern __shared__ char smem[];
    const uint32_t sb = smem_u32(smem);
    const int t    = threadIdx.x;
    const int w    = t >> 5;
    const int lane = t & 31;
    const int wm   = w >> 2;          // 0..1 (64-row band)
    const int wn   = w & 3;           // 0..3 (64-col band)

    float* bias_s = (float*)(smem + OFF_BIAS);
    int*   seg_s  = (int*)(smem + OFF_SEG);

    // ---- issue cp.async for first tile immediately ----
    {
        const int rowbase = blockIdx.x * 128;
#pragma unroll
        for (int j = 0; j < 16; j++) {
            int idx = j * 256 + t;
            int r = idx >> 5, q = idx & 31;
            uint32_t dst = (sb + OFF_A + (uint32_t)r * 512u + (uint32_t)q * 16u) ^ RSWZ(r);
            cpasync16(dst, g_xh + (size_t)(rowbase + r) * DIM + q * 8);
        }
        CP_COMMIT();
        if (t < 128) seg_s[t] = bidx[rowbase + t];
    }

    bias_s[t] = b1[t];

    // ---- W1 fp16 -> SMEM [n][k] 512B rows, swizzled (once per CTA) ----
    {
        const uint4* wsrc = (const uint4*)g_W1h;
#pragma unroll
        for (int j = 0; j < 32; j++) {
            int idx = j * 256 + t;
            int row = idx >> 5, q = idx & 31;
            uint32_t addr = (sb + OFF_W + (uint32_t)row * 512u + (uint32_t)q * 16u) ^ RSWZ(row);
            sts16(addr, wsrc[idx]);
        }
    }
    CP_WAIT0();
    __syncthreads();

    const uint32_t xmask  = RSWZ(lane);
    const uint32_t a_base = sb + OFF_A + (uint32_t)(wm * 64 + (lane & 15)) * 512u + (uint32_t)(lane >> 4) * 16u;
    const uint32_t b_base = sb + OFF_W + (uint32_t)(wn * 64 + (lane & 15)) * 512u + (uint32_t)(lane >> 4) * 16u;
    const int colbase = wn * 64 + 2 * (lane & 3);

    for (int tile = blockIdx.x; tile < M_TILES; tile += GRID_A) {
        // ---- HMMA mainloop: K = 256 in 16 steps; frag double buffering ----
        float acc[4][8][4];
#pragma unroll
        for (int mi = 0; mi < 4; mi++)
#pragma unroll
            for (int ni = 0; ni < 8; ni++)
#pragma unroll
                for (int d = 0; d < 4; d++) acc[mi][ni][d] = 0.0f;

        uint32_t af0[4][4], bf0[4][4], af1[4][4], bf1[4][4];

        // prologue: load ks=0 into set 0
#pragma unroll
        for (int mi = 0; mi < 4; mi++)
            ldmat_x4(af0[mi], (a_base + (uint32_t)mi * 8192u) ^ xmask);
#pragma unroll
        for (int p = 0; p < 4; p++)
            ldmat_x4(bf0[p], (b_base + (uint32_t)p * 8192u) ^ xmask);

#pragma unroll
        for (int ks = 0; ks < 16; ks++) {
            const uint32_t koff_n = (uint32_t)(ks + 1) * 32u;
            if (ks & 1) {
                if (ks < 15) {
#pragma unroll
                    for (int mi = 0; mi < 4; mi++)
                        ldmat_x4(af0[mi], (a_base + (uint32_t)mi * 8192u + koff_n) ^ xmask);
#pragma unroll
                    for (int p = 0; p < 4; p++)
                        ldmat_x4(bf0[p], (b_base + (uint32_t)p * 8192u + koff_n) ^ xmask);
                }
#pragma unroll
                for (int p = 0; p < 4; p++)
#pragma unroll
                    for (int mi = 0; mi < 4; mi++) {
                        mma16816(acc[mi][2 * p],     af1[mi], bf1[p][0], bf1[p][2]);
                        mma16816(acc[mi][2 * p + 1], af1[mi], bf1[p][1], bf1[p][3]);
                    }
            } else {
                if (ks < 15) {
#pragma unroll
                    for (int mi = 0; mi < 4; mi++)
                        ldmat_x4(af1[mi], (a_base + (uint32_t)mi * 8192u + koff_n) ^ xmask);
#pragma unroll
                    for (int p = 0; p < 4; p++)
                        ldmat_x4(bf1[p], (b_base + (uint32_t)p * 8192u + koff_n) ^ xmask);
                }
#pragma unroll
                for (int p = 0; p < 4; p++)
#pragma unroll
                    for (int mi = 0; mi < 4; mi++) {
                        mma16816(acc[mi][2 * p],     af0[mi], bf0[p][0], bf0[p][2]);
                        mma16816(acc[mi][2 * p + 1], af0[mi], bf0[p][1], bf0[p][3]);
                    }
            }
        }
        __syncthreads();   // all warps done reading A

        // ---- prefetch next x tile via cp.async ----
        const int  ntile = tile + GRID_A;
        const bool more  = ntile < M_TILES;
        int segnext = 0;
        if (more) {
            const int nrow = ntile * 128;
#pragma unroll
            for (int j = 0; j < 16; j++) {
                int idx = j * 256 + t;
                int r = idx >> 5, q = idx & 31;
                uint32_t dst = (sb + OFF_A + (uint32_t)r * 512u + (uint32_t)q * 16u) ^ RSWZ(r);
                cpasync16(dst, g_xh + (size_t)(nrow + r) * DIM + q * 8);
            }
            if (t < 128) segnext = bidx[nrow + t];
        }
        CP_COMMIT();

        // ---- barrier-free epilogue: bias + shuffle segmented reduce ----
        {
            float bb[16];
#pragma unroll
            for (int i = 0; i < 16; i++) bb[i] = bias_s[colbase + (i >> 1) * 8 + (i & 1)];
#pragma unroll
            for (int mi = 0; mi < 4; mi++)
#pragma unroll
                for (int ni = 0; ni < 8; ni++)
#pragma unroll
                    for (int d = 0; d < 4; d++)
                        acc[mi][ni][d] += bb[ni * 2 + (d & 1)];

            float ps[16], pm[16];
            int pseg = -1;

#pragma unroll
            for (int b = 0; b < 8; b++) {
                const int mi = b >> 1, rh = b & 1;
                const int rb = wm * 64 + mi * 16 + rh * 8;
                const int seg0 = seg_s[rb];
                const int seg7 = seg_s[rb + 7];

                float v[16];
#pragma unroll
                for (int ni = 0; ni < 8; ni++) {
                    v[ni * 2]     = acc[mi][ni][2 * rh];
                    v[ni * 2 + 1] = acc[mi][ni][2 * rh + 1];
                }

                if (seg0 == seg7) {
                    if (pseg == seg0) {
#pragma unroll
                        for (int i = 0; i < 16; i++) {
                            ps[i] += v[i];
                            pm[i] = fmaxf(pm[i], v[i]);
                        }
                    } else {
                        if (pseg >= 0) {
#pragma unroll
                            for (int r = 4; r <= 16; r <<= 1)
#pragma unroll
                                for (int i = 0; i < 16; i++) {
                                    ps[i] += __shfl_xor_sync(0xFFFFFFFFu, ps[i], r);
                                    pm[i] = fmaxf(pm[i], __shfl_xor_sync(0xFFFFFFFFu, pm[i], r));
                                }
                            unsigned gb = (unsigned)pseg * DIM + colbase;
                            if (lane < 4) {
#pragma unroll
                                for (int i = 0; i < 16; i++)
                                    atomicAdd(&g_seg_sum[gb + (i >> 1) * 8 + (i & 1)], ps[i]);
                            } else if (lane < 8) {
#pragma unroll
                                for (int i = 0; i < 16; i++)
                                    atomicMax(&g_seg_max[gb + (i >> 1) * 8 + (i & 1)], enc_f(pm[i]));
                            }
                        }
#pragma unroll
                        for (int i = 0; i < 16; i++) { ps[i] = v[i]; pm[i] = v[i]; }
                        pseg = seg0;
                    }
                } else {
                    const int myseg = seg_s[rb + (lane >> 2)];
                    unsigned gb = (unsigned)myseg * DIM + colbase;
#pragma unroll
                    for (int i = 0; i < 16; i++) {
                        atomicAdd(&g_seg_sum[gb + (i >> 1) * 8 + (i & 1)], v[i]);
                        atomicMax(&g_seg_max[gb + (i >> 1) * 8 + (i & 1)], enc_f(v[i]));
                    }
                }
            }
            if (pseg >= 0) {
#pragma unroll
                for (int r = 4; r <= 16; r <<= 1)
#pragma unroll
                    for (int i = 0; i < 16; i++) {
                        ps[i] += __shfl_xor_sync(0xFFFFFFFFu, ps[i], r);
                        pm[i] = fmaxf(pm[i], __shfl_xor_sync(0xFFFFFFFFu, pm[i], r));
                    }
                unsigned gb = (unsigned)pseg * DIM + colbase;
                if (lane < 4) {
#pragma unroll
                    for (int i = 0; i < 16; i++)
                        atomicAdd(&g_seg_sum[gb + (i >> 1) * 8 + (i & 1)], ps[i]);
                } else if (lane < 8) {
#pragma unroll
                    for (int i = 0; i < 16; i++)
                        atomicMax(&g_seg_max[gb + (i >> 1) * 8 + (i & 1)], enc_f(pm[i]));
                }
            }
        }

        CP_WAIT0();
        __syncthreads();
        if (more && t < 128) seg_s[t] = segnext;
    }
}

// ---------------- proj: HMMA fp16 GEMM + fused MLP-4 scatter ------------------
__global__ void __launch_bounds__(256, 2) proj_scatter(
    const int*   __restrict__ bidx,
    const float* __restrict__ bp,
    float4*      __restrict__ out4)
{
    extern __shared__ char smem[];
    const uint32_t sb = smem_u32(smem);
    const int t    = threadIdx.x;
    const int w    = t >> 5;
    const int lane = t & 31;
    const int wn   = w;
    const int tileM = blockIdx.x * 32;

    int*   cnt_s  = (int*)(smem + P_OFF_CNT);
    float* invc_s = (float*)(smem + P_OFF_INV);
    float* bp_s   = (float*)(smem + P_OFF_BP);
    float* outs   = (float*)(smem + P_OFF_OUT);

    if (t < 32) {
        int cn = g_rowstart[tileM + t + 1] - g_rowstart[tileM + t];
        cnt_s[t]  = cn;
        invc_s[t] = 1.0f / (float)max(cn, 1);
    }
    bp_s[t] = bp[t];

    const uint32_t xmask  = RSWZ(lane);
    const uint32_t a_base = sb + P_OFF_XA + (uint32_t)(lane & 15) * 128u + (uint32_t)(lane >> 4) * 16u;
    const uint32_t b_base = sb + P_OFF_B  + (uint32_t)(wn * 32 + (lane & 15)) * 128u + (uint32_t)(lane >> 4) * 16u;

    float acc[2][4][4];
#pragma unroll
    for (int mi = 0; mi < 2; mi++)
#pragma unroll
        for (int ni = 0; ni < 4; ni++)
#pragma unroll
            for (int d = 0; d < 4; d++) acc[mi][ni][d] = 0.0f;

#pragma unroll 1
    for (int kc = 0; kc < 8; kc++) {
        __syncthreads();

#pragma unroll
        for (int i = 0; i < 2; i++) {
            int idx = i * 256 + t;
            int row = idx >> 4, q = idx & 15;
            float4 va;
            if (kc < 4) {
                va = *(const float4*)&g_seg_sum[(size_t)(tileM + row) * DIM + kc * 64 + q * 4];
                float iv = invc_s[row];
                va.x *= iv; va.y *= iv; va.z *= iv; va.w *= iv;
            } else {
                uint4 u = *(const uint4*)&g_seg_max[(size_t)(tileM + row) * DIM + (kc - 4) * 64 + q * 4];
                if (cnt_s[row] > 0) {
                    va.x = dec_f(u.x); va.y = dec_f(u.y); va.z = dec_f(u.z); va.w = dec_f(u.w);
                } else {
                    va.x = va.y = va.z = va.w = 0.0f;
                }
            }
            __half2 h0 = __floats2half2_rn(va.x, va.y);
            __half2 h1 = __floats2half2_rn(va.z, va.w);
            uint32_t addr = (sb + P_OFF_XA + (uint32_t)row * 128u + (uint32_t)q * 8u) ^ RSWZ(row);
            sts8(addr, *(uint32_t*)&h0, *(uint32_t*)&h1);
        }
#pragma unroll
        for (int i = 0; i < 8; i++) {
            int idx = i * 256 + t;
            int row = idx >> 3, q = idx & 7;
            uint4 v = ((const uint4*)g_Wph)[row * 64 + kc * 8 + q];
            uint32_t addr = (sb + P_OFF_B + (uint32_t)row * 128u + (uint32_t)q * 16u) ^ RSWZ(row);
            sts16(addr, v);
        }
        __syncthreads();

#pragma unroll
        for (int ks = 0; ks < 4; ks++) {
            const uint32_t koff = (uint32_t)ks * 32u;
            uint32_t a0[4], a1[4];
            ldmat_x4(a0, (a_base + koff) ^ xmask);
            ldmat_x4(a1, (a_base + 16u * 128u + koff) ^ xmask);
#pragma unroll
            for (int p = 0; p < 2; p++) {
                uint32_t bf[4];
                ldmat_x4(bf, (b_base + (uint32_t)p * 2048u + koff) ^ xmask);
                mma16816(acc[0][2 * p],     a0, bf[0], bf[2]);
                mma16816(acc[0][2 * p + 1], a0, bf[1], bf[3]);
                mma16816(acc[1][2 * p],     a1, bf[0], bf[2]);
                mma16816(acc[1][2 * p + 1], a1, bf[1], bf[3]);
            }
        }
    }

    {
        const int r0 = lane >> 2;
        const int c0 = wn * 32 + 2 * (lane & 3);
#pragma unroll
        for (int mi = 0; mi < 2; mi++)
#pragma unroll
            for (int ni = 0; ni < 4; ni++) {
                int col = c0 + ni * 8;
                float bb0 = bp_s[col], bb1 = bp_s[col + 1];
                int rr = r0 + mi * 16;
                outs[rr * OUT_LD + col]           = acc[mi][ni][0] + bb0;
                outs[rr * OUT_LD + col + 1]       = acc[mi][ni][1] + bb1;
                outs[(rr + 8) * OUT_LD + col]     = acc[mi][ni][2] + bb0;
                outs[(rr + 8) * OUT_LD + col + 1] = acc[mi][ni][3] + bb1;
            }
    }
    __syncthreads();

    const int rstart = g_rowstart[tileM];
    const int rend   = g_rowstart[tileM + 32];
    const int cq     = t & 63;
    int r = rstart + (t >> 6);
    for (; r + 12 < rend; r += 16) {
        int s0 = __ldg(&bidx[r])      - tileM;
        int s1 = __ldg(&bidx[r +  4]) - tileM;
        int s2 = __ldg(&bidx[r +  8]) - tileM;
        int s3 = __ldg(&bidx[r + 12]) - tileM;
        float4 v0 = *(const float4*)&outs[s0 * OUT_LD + cq * 4];
        float4 v1 = *(const float4*)&outs[s1 * OUT_LD + cq * 4];
        float4 v2 = *(const float4*)&outs[s2 * OUT_LD + cq * 4];
        float4 v3 = *(const float4*)&outs[s3 * OUT_LD + cq * 4];
        out4[(size_t)r * 64 + cq]        = v0;
        out4[(size_t)(r +  4) * 64 + cq] = v1;
        out4[(size_t)(r +  8) * 64 + cq] = v2;
        out4[(size_t)(r + 12) * 64 + cq] = v3;
    }
    for (; r < rend; r += 4) {
        int s0 = __ldg(&bidx[r]) - tileM;
        out4[(size_t)r * 64 + cq] = *(const float4*)&outs[s0 * OUT_LD + cq * 4];
    }
}

// ---------------- launch -----------------------------------------------------
extern "C" void kernel_launch(void* const* d_in, const int* in_sizes, int n_in,
                              void* d_out, int out_size) {
    const float* x    = (const float*)d_in[0];
    const int*   bidx = (const int*)  d_in[1];
    const float* W1   = (const float*)d_in[2];
    const float* b1   = (const float*)d_in[3];
    const float* Wp   = (const float*)d_in[4];
    const float* bp   = (const float*)d_in[5];

    cudaFuncSetAttribute(gemm_pool_mma, cudaFuncAttributeMaxDynamicSharedMemorySize,
                         SMEM_A_BYTES);
    cudaFuncSetAttribute(proj_scatter, cudaFuncAttributeMaxDynamicSharedMemorySize,
                         SMEM_P_BYTES);

    prep_kernel<<<32768, 256>>>(x, W1, Wp, bidx);

    gemm_pool_mma<<<GRID_A, 256, SMEM_A_BYTES>>>(bidx, b1);

    proj_scatter<<<NSEG / 32, 256, SMEM_P_BYTES>>>(bidx, bp, (float4*)d_out);
}

// round 13
// speedup vs baseline: 1.1638x; 1.1638x over previous
#include <cuda_runtime.h>
#include <cuda_fp16.h>
#include <cstdint>

#define N_ROWS 524288
#define DIM 256
#define NSEG 8192
#define M_TILES 4096      // 128-row M tiles
#define GRID_A 148

// ---------------- scratch (device globals) ----------------------------------
__device__ float    g_seg_sum[NSEG * DIM];
__device__ unsigned g_seg_max[NSEG * DIM];
__device__ int      g_rowstart[NSEG + 1];
__device__ __half   g_W1h[DIM * DIM];
__device__ __half   g_Wph[DIM * 2 * DIM];

// ---------------- helpers ----------------------------------------------------
__device__ __forceinline__ uint32_t smem_u32(const void* p) {
    uint32_t a;
    asm("{ .reg .u64 t; cvta.to.shared.u64 t, %1; cvt.u32.u64 %0, t; }" : "=r"(a) : "l"(p));
    return a;
}
__device__ __forceinline__ void ldmat_x4(uint32_t r[4], uint32_t addr) {
    asm volatile("ldmatrix.sync.aligned.m8n8.x4.shared.b16 {%0,%1,%2,%3}, [%4];"
                 : "=r"(r[0]), "=r"(r[1]), "=r"(r[2]), "=r"(r[3]) : "r"(addr));
}
__device__ __forceinline__ void mma16816(float d[4], const uint32_t a[4],
                                         uint32_t b0, uint32_t b1) {
    asm volatile("mma.sync.aligned.m16n8k16.row.col.f32.f16.f16.f32 "
                 "{%0,%1,%2,%3}, {%4,%5,%6,%7}, {%8,%9}, {%0,%1,%2,%3};"
                 : "+f"(d[0]), "+f"(d[1]), "+f"(d[2]), "+f"(d[3])
                 : "r"(a[0]), "r"(a[1]), "r"(a[2]), "r"(a[3]), "r"(b0), "r"(b1));
}
__device__ __forceinline__ void sts8(uint32_t addr, uint32_t u0, uint32_t u1) {
    asm volatile("st.shared.v2.b32 [%0], {%1,%2};" :: "r"(addr), "r"(u0), "r"(u1) : "memory");
}
__device__ __forceinline__ void sts16(uint32_t addr, uint4 v) {
    asm volatile("st.shared.v4.b32 [%0], {%1,%2,%3,%4};"
                 :: "r"(addr), "r"(v.x), "r"(v.y), "r"(v.z), "r"(v.w) : "memory");
}
__device__ __forceinline__ unsigned enc_f(float f) {
    unsigned i = __float_as_uint(f);
    return (i & 0x80000000u) ? ~i : (i | 0x80000000u);
}
__device__ __forceinline__ float dec_f(unsigned u) {
    return __uint_as_float((u & 0x80000000u) ? (u & 0x7FFFFFFFu) : ~u);
}
#define RSWZ(row) (((uint32_t)((row) & 7)) << 4)

// ---------------- kernel A smem layout (512B rows, swizzled) ----------------
#define OFF_W    0u          // 256 rows x 512B = 131072
#define OFF_A    131072u     // 128 rows x 512B = 65536
#define OFF_BIAS 196608u     // 1024
#define OFF_SEG  197632u     // 512
#define SMEM_A_BYTES 198144

// ---------------- proj smem layout (tile M=32) --------------------------------
#define P_OFF_B    0u        // Wp chunk: 256 x 128B = 32768
#define P_OFF_XA   32768u    // xpool chunk: 32 x 128B = 4096
#define P_OFF_OUT  36864u    // 32 x 260 x 4 = 33280
#define P_OFF_CNT  70144u    // 128
#define P_OFF_INV  70272u    // 128
#define P_OFF_BP   70400u    // 1024
#define SMEM_P_BYTES 71424
#define OUT_LD 260

// ---------------- prep: init + wconv + rowstart (role blocks) ----------------
__global__ void prep_kernel(const float* __restrict__ W1,
                            const float* __restrict__ Wp,
                            const int*   __restrict__ bidx)
{
    const int b = blockIdx.x;
    const int t = threadIdx.x;

    if (b < 8192) {                       // init
        int i = b * 256 + t;
        g_seg_sum[i] = 0.0f;
        g_seg_max[i] = 0u;
    } else if (b < 8192 + 384) {          // wconv
        int i = (b - 8192) * 256 + t;
        if (i < 32768) {
            float2 f = ((const float2*)W1)[i];
            ((__half2*)g_W1h)[i] = __floats2half2_rn(f.x, f.y);
        } else {
            int j = i - 32768;
            float2 f = ((const float2*)Wp)[j];
            ((__half2*)g_Wph)[j] = __floats2half2_rn(f.x, f.y);
        }
    } else {                              // rowstart
        int s = (b - 8192 - 384) * 256 + t;
        int lo = 0, hi = N_ROWS;
        while (lo < hi) {
            int mid = (lo + hi) >> 1;
            if (__ldg(&bidx[mid]) < s) lo = mid + 1; else hi = mid;
        }
        g_rowstart[s] = lo;
        if (s == 0) g_rowstart[NSEG] = N_ROWS;
    }
}

// convert one batch of 8 float4 (fp32) to fp16 smem, batch b covers
// idx = b*2048 + j*256 + t over the 8192-float4 tile (row = idx>>6, q = idx&63)
__device__ __forceinline__ void cvt_store_batch(uint32_t sb, int bch, int t,
                                                const float4 pf[8]) {
#pragma unroll
    for (int j = 0; j < 8; j++) {
        int idx = bch * 2048 + j * 256 + t;
        int r = idx >> 6, q = idx & 63;
        __half2 h0 = __floats2half2_rn(pf[j].x, pf[j].y);
        __half2 h1 = __floats2half2_rn(pf[j].z, pf[j].w);
        uint32_t addr = (sb + OFF_A + (uint32_t)r * 512u + (uint32_t)q * 8u) ^ RSWZ(r);
        sts8(addr, *(uint32_t*)&h0, *(uint32_t*)&h1);
    }
}

// ---------------- kernel A: HMMA GEMM + shuffle segmented reduce -------------
// 256 thr = 8 warps (2M x 4N); warp tile 64x64; fp32 x converted in-kernel,
// pipelined behind the epilogue (batch0 prefetch + 2-deep load/convert chain).
__global__ void __launch_bounds__(256, 1) gemm_pool_mma(
    const float* __restrict__ x,
    const int*   __restrict__ bidx,
    const float* __restrict__ b1)
{
    extern __shared__ char smem[];
    const uint32_t sb = smem_u32(smem);
    const int t    = threadIdx.x;
    const int w    = t >> 5;
    const int lane = t & 31;
    const int wm   = w >> 2;          // 0..1 (64-row band)
    const int wn   = w & 3;           // 0..3 (64-col band)

    float* bias_s = (float*)(smem + OFF_BIAS);
    int*   seg_s  = (int*)(smem + OFF_SEG);

    bias_s[t] = b1[t];

    // ---- first tile: load fp32 -> convert -> smem (4 batches, pipelined) ----
    {
        const int rowbase = blockIdx.x * 128;
        const float4* xb4 = (const float4*)(x + (size_t)rowbase * DIM);
        float4 pf[8];
#pragma unroll
        for (int j = 0; j < 8; j++) pf[j] = xb4[j * 256 + t];
#pragma unroll
        for (int bch = 0; bch < 4; bch++) {
            float4 nx[8];
            if (bch < 3) {
#pragma unroll
                for (int j = 0; j < 8; j++) nx[j] = xb4[(bch + 1) * 2048 + j * 256 + t];
            }
            cvt_store_batch(sb, bch, t, pf);
            if (bch < 3) {
#pragma unroll
                for (int j = 0; j < 8; j++) pf[j] = nx[j];
            }
        }
        if (t < 128) seg_s[t] = bidx[rowbase + t];
    }

    // ---- W1 fp16 -> SMEM [n][k] 512B rows, swizzled (once per CTA) ----
    {
        const uint4* wsrc = (const uint4*)g_W1h;
#pragma unroll
        for (int j = 0; j < 32; j++) {
            int idx = j * 256 + t;
            int row = idx >> 5, q = idx & 31;
            uint32_t addr = (sb + OFF_W + (uint32_t)row * 512u + (uint32_t)q * 16u) ^ RSWZ(row);
            sts16(addr, wsrc[idx]);
        }
    }
    __syncthreads();

    const uint32_t xmask  = RSWZ(lane);
    const uint32_t a_base = sb + OFF_A + (uint32_t)(wm * 64 + (lane & 15)) * 512u + (uint32_t)(lane >> 4) * 16u;
    const uint32_t b_base = sb + OFF_W + (uint32_t)(wn * 64 + (lane & 15)) * 512u + (uint32_t)(lane >> 4) * 16u;
    const int colbase = wn * 64 + 2 * (lane & 3);

    for (int tile = blockIdx.x; tile < M_TILES; tile += GRID_A) {
        // ---- HMMA mainloop: K = 256 in 16 steps; warp tile 64x64 ----
        float acc[4][8][4];
#pragma unroll
        for (int mi = 0; mi < 4; mi++)
#pragma unroll
            for (int ni = 0; ni < 8; ni++)
#pragma unroll
                for (int d = 0; d < 4; d++) acc[mi][ni][d] = 0.0f;

#pragma unroll 2
        for (int ks = 0; ks < 16; ks++) {
            const uint32_t koff = (uint32_t)ks * 32u;
            uint32_t af[4][4];
#pragma unroll
            for (int mi = 0; mi < 4; mi++)
                ldmat_x4(af[mi], (a_base + (uint32_t)mi * 8192u + koff) ^ xmask);
#pragma unroll
            for (int p = 0; p < 4; p++) {
                uint32_t bf[4];
                ldmat_x4(bf, (b_base + (uint32_t)p * 8192u + koff) ^ xmask);
#pragma unroll
                for (int mi = 0; mi < 4; mi++) {
                    mma16816(acc[mi][2 * p],     af[mi], bf[0], bf[2]);
                    mma16816(acc[mi][2 * p + 1], af[mi], bf[1], bf[3]);
                }
            }
        }
        __syncthreads();   // all warps done reading A-smem

        // ---- prefetch batch0 of next x tile (fp32) into regs ----
        const int  ntile = tile + GRID_A;
        const bool more  = ntile < M_TILES;
        const float4* xn4 = (const float4*)(x + (size_t)ntile * 128 * DIM);
        float4 pf[8];
        int segnext = 0;
        if (more) {
#pragma unroll
            for (int j = 0; j < 8; j++) pf[j] = xn4[j * 256 + t];
            if (t < 128) segnext = bidx[ntile * 128 + t];
        }

        // ---- barrier-free epilogue: bias + shuffle segmented reduce ----
        {
            float bb[16];
#pragma unroll
            for (int i = 0; i < 16; i++) bb[i] = bias_s[colbase + (i >> 1) * 8 + (i & 1)];
#pragma unroll
            for (int mi = 0; mi < 4; mi++)
#pragma unroll
                for (int ni = 0; ni < 8; ni++)
#pragma unroll
                    for (int d = 0; d < 4; d++)
                        acc[mi][ni][d] += bb[ni * 2 + (d & 1)];

            float ps[16], pm[16];
            int pseg = -1;

#pragma unroll
            for (int b = 0; b < 8; b++) {
                const int mi = b >> 1, rh = b & 1;
                const int rb = wm * 64 + mi * 16 + rh * 8;
                const int seg0 = seg_s[rb];
                const int seg7 = seg_s[rb + 7];

                float v[16];
#pragma unroll
                for (int ni = 0; ni < 8; ni++) {
                    v[ni * 2]     = acc[mi][ni][2 * rh];
                    v[ni * 2 + 1] = acc[mi][ni][2 * rh + 1];
                }

                if (seg0 == seg7) {
                    if (pseg == seg0) {
#pragma unroll
                        for (int i = 0; i < 16; i++) {
                            ps[i] += v[i];
                            pm[i] = fmaxf(pm[i], v[i]);
                        }
                    } else {
                        if (pseg >= 0) {
#pragma unroll
                            for (int r = 4; r <= 16; r <<= 1)
#pragma unroll
                                for (int i = 0; i < 16; i++) {
                                    ps[i] += __shfl_xor_sync(0xFFFFFFFFu, ps[i], r);
                                    pm[i] = fmaxf(pm[i], __shfl_xor_sync(0xFFFFFFFFu, pm[i], r));
                                }
                            unsigned gb = (unsigned)pseg * DIM + colbase;
                            if (lane < 4) {
#pragma unroll
                                for (int i = 0; i < 16; i++)
                                    atomicAdd(&g_seg_sum[gb + (i >> 1) * 8 + (i & 1)], ps[i]);
                            } else if (lane < 8) {
#pragma unroll
                                for (int i = 0; i < 16; i++)
                                    atomicMax(&g_seg_max[gb + (i >> 1) * 8 + (i & 1)], enc_f(pm[i]));
                            }
                        }
#pragma unroll
                        for (int i = 0; i < 16; i++) { ps[i] = v[i]; pm[i] = v[i]; }
                        pseg = seg0;
                    }
                } else {
                    const int myseg = seg_s[rb + (lane >> 2)];
                    unsigned gb = (unsigned)myseg * DIM + colbase;
#pragma unroll
                    for (int i = 0; i < 16; i++) {
                        atomicAdd(&g_seg_sum[gb + (i >> 1) * 8 + (i & 1)], v[i]);
                        atomicMax(&g_seg_max[gb + (i >> 1) * 8 + (i & 1)], enc_f(v[i]));
                    }
                }
            }
            if (pseg >= 0) {
#pragma unroll
                for (int r = 4; r <= 16; r <<= 1)
#pragma unroll
                    for (int i = 0; i < 16; i++) {
                        ps[i] += __shfl_xor_sync(0xFFFFFFFFu, ps[i], r);
                        pm[i] = fmaxf(pm[i], __shfl_xor_sync(0xFFFFFFFFu, pm[i], r));
                    }
                unsigned gb = (unsigned)pseg * DIM + colbase;
                if (lane < 4) {
#pragma unroll
                    for (int i = 0; i < 16; i++)
                        atomicAdd(&g_seg_sum[gb + (i >> 1) * 8 + (i & 1)], ps[i]);
                } else if (lane < 8) {
#pragma unroll
                    for (int i = 0; i < 16; i++)
                        atomicMax(&g_seg_max[gb + (i >> 1) * 8 + (i & 1)], enc_f(pm[i]));
                }
            }
        }

        // ---- remaining batches: load(b+1) then convert/store(b); acc dead ----
        if (more) {
#pragma unroll
            for (int bch = 0; bch < 4; bch++) {
                float4 nx[8];
                if (bch < 3) {
#pragma unroll
                    for (int j = 0; j < 8; j++) nx[j] = xn4[(bch + 1) * 2048 + j * 256 + t];
                }
                cvt_store_batch(sb, bch, t, pf);
                if (bch < 3) {
#pragma unroll
                    for (int j = 0; j < 8; j++) pf[j] = nx[j];
                }
            }
        }
        __syncthreads();   // A(next) visible; all seg_s reads done
        if (more && t < 128) seg_s[t] = segnext;   // ordered before next epilogue by next post-mainloop sync
    }
}

// ---------------- proj: HMMA fp16 GEMM + fused MLP-4 scatter ------------------
__global__ void __launch_bounds__(256, 2) proj_scatter(
    const int*   __restrict__ bidx,
    const float* __restrict__ bp,
    float4*      __restrict__ out4)
{
    extern __shared__ char smem[];
    const uint32_t sb = smem_u32(smem);
    const int t    = threadIdx.x;
    const int w    = t >> 5;
    const int lane = t & 31;
    const int wn   = w;
    const int tileM = blockIdx.x * 32;

    int*   cnt_s  = (int*)(smem + P_OFF_CNT);
    float* invc_s = (float*)(smem + P_OFF_INV);
    float* bp_s   = (float*)(smem + P_OFF_BP);
    float* outs   = (float*)(smem + P_OFF_OUT);

    if (t < 32) {
        int cn = g_rowstart[tileM + t + 1] - g_rowstart[tileM + t];
        cnt_s[t]  = cn;
        invc_s[t] = 1.0f / (float)max(cn, 1);
    }
    bp_s[t] = bp[t];

    const uint32_t xmask  = RSWZ(lane);
    const uint32_t a_base = sb + P_OFF_XA + (uint32_t)(lane & 15) * 128u + (uint32_t)(lane >> 4) * 16u;
    const uint32_t b_base = sb + P_OFF_B  + (uint32_t)(wn * 32 + (lane & 15)) * 128u + (uint32_t)(lane >> 4) * 16u;

    float acc[2][4][4];
#pragma unroll
    for (int mi = 0; mi < 2; mi++)
#pragma unroll
        for (int ni = 0; ni < 4; ni++)
#pragma unroll
            for (int d = 0; d < 4; d++) acc[mi][ni][d] = 0.0f;

#pragma unroll 1
    for (int kc = 0; kc < 8; kc++) {
        __syncthreads();

#pragma unroll
        for (int i = 0; i < 2; i++) {
            int idx = i * 256 + t;
            int row = idx >> 4, q = idx & 15;
            float4 va;
            if (kc < 4) {
                va = *(const float4*)&g_seg_sum[(size_t)(tileM + row) * DIM + kc * 64 + q * 4];
                float iv = invc_s[row];
                va.x *= iv; va.y *= iv; va.z *= iv; va.w *= iv;
            } else {
                uint4 u = *(const uint4*)&g_seg_max[(size_t)(tileM + row) * DIM + (kc - 4) * 64 + q * 4];
                if (cnt_s[row] > 0) {
                    va.x = dec_f(u.x); va.y = dec_f(u.y); va.z = dec_f(u.z); va.w = dec_f(u.w);
                } else {
                    va.x = va.y = va.z = va.w = 0.0f;
                }
            }
            __half2 h0 = __floats2half2_rn(va.x, va.y);
            __half2 h1 = __floats2half2_rn(va.z, va.w);
            uint32_t addr = (sb + P_OFF_XA + (uint32_t)row * 128u + (uint32_t)q * 8u) ^ RSWZ(row);
            sts8(addr, *(uint32_t*)&h0, *(uint32_t*)&h1);
        }
#pragma unroll
        for (int i = 0; i < 8; i++) {
            int idx = i * 256 + t;
            int row = idx >> 3, q = idx & 7;
            uint4 v = ((const uint4*)g_Wph)[row * 64 + kc * 8 + q];
            uint32_t addr = (sb + P_OFF_B + (uint32_t)row * 128u + (uint32_t)q * 16u) ^ RSWZ(row);
            sts16(addr, v);
        }
        __syncthreads();

#pragma unroll
        for (int ks = 0; ks < 4; ks++) {
            const uint32_t koff = (uint32_t)ks * 32u;
            uint32_t a0[4], a1[4];
            ldmat_x4(a0, (a_base + koff) ^ xmask);
            ldmat_x4(a1, (a_base + 16u * 128u + koff) ^ xmask);
#pragma unroll
            for (int p = 0; p < 2; p++) {
                uint32_t bf[4];
                ldmat_x4(bf, (b_base + (uint32_t)p * 2048u + koff) ^ xmask);
                mma16816(acc[0][2 * p],     a0, bf[0], bf[2]);
                mma16816(acc[0][2 * p + 1], a0, bf[1], bf[3]);
                mma16816(acc[1][2 * p],     a1, bf[0], bf[2]);
                mma16816(acc[1][2 * p + 1], a1, bf[1], bf[3]);
            }
        }
    }

    {
        const int r0 = lane >> 2;
        const int c0 = wn * 32 + 2 * (lane & 3);
#pragma unroll
        for (int mi = 0; mi < 2; mi++)
#pragma unroll
            for (int ni = 0; ni < 4; ni++) {
                int col = c0 + ni * 8;
                float bb0 = bp_s[col], bb1 = bp_s[col + 1];
                int rr = r0 + mi * 16;
                outs[rr * OUT_LD + col]           = acc[mi][ni][0] + bb0;
                outs[rr * OUT_LD + col + 1]       = acc[mi][ni][1] + bb1;
                outs[(rr + 8) * OUT_LD + col]     = acc[mi][ni][2] + bb0;
                outs[(rr + 8) * OUT_LD + col + 1] = acc[mi][ni][3] + bb1;
            }
    }
    __syncthreads();

    const int rstart = g_rowstart[tileM];
    const int rend   = g_rowstart[tileM + 32];
    const int cq     = t & 63;
    int r = rstart + (t >> 6);
    for (; r + 12 < rend; r += 16) {
        int s0 = __ldg(&bidx[r])      - tileM;
        int s1 = __ldg(&bidx[r +  4]) - tileM;
        int s2 = __ldg(&bidx[r +  8]) - tileM;
        int s3 = __ldg(&bidx[r + 12]) - tileM;
        float4 v0 = *(const float4*)&outs[s0 * OUT_LD + cq * 4];
        float4 v1 = *(const float4*)&outs[s1 * OUT_LD + cq * 4];
        float4 v2 = *(const float4*)&outs[s2 * OUT_LD + cq * 4];
        float4 v3 = *(const float4*)&outs[s3 * OUT_LD + cq * 4];
        out4[(size_t)r * 64 + cq]        = v0;
        out4[(size_t)(r +  4) * 64 + cq] = v1;
        out4[(size_t)(r +  8) * 64 + cq] = v2;
        out4[(size_t)(r + 12) * 64 + cq] = v3;
    }
    for (; r < rend; r += 4) {
        int s0 = __ldg(&bidx[r]) - tileM;
        out4[(size_t)r * 64 + cq] = *(const float4*)&outs[s0 * OUT_LD + cq * 4];
    }
}

// ---------------- launch -----------------------------------------------------
extern "C" void kernel_launch(void* const* d_in, const int* in_sizes, int n_in,
                              void* d_out, int out_size) {
    const float* x    = (const float*)d_in[0];
    const int*   bidx = (const int*)  d_in[1];
    const float* W1   = (const float*)d_in[2];
    const float* b1   = (const float*)d_in[3];
    const float* Wp   = (const float*)d_in[4];
    const float* bp   = (const float*)d_in[5];

    cudaFuncSetAttribute(gemm_pool_mma, cudaFuncAttributeMaxDynamicSharedMemorySize,
                         SMEM_A_BYTES);
    cudaFuncSetAttribute(proj_scatter, cudaFuncAttributeMaxDynamicSharedMemorySize,
                         SMEM_P_BYTES);

    prep_kernel<<<8192 + 384 + 32, 256>>>(W1, Wp, bidx);

    gemm_pool_mma<<<GRID_A, 256, SMEM_A_BYTES>>>(x, bidx, b1);

    proj_scatter<<<NSEG / 32, 256, SMEM_P_BYTES>>>(bidx, bp, (float4*)d_out);
}

// round 14
// speedup vs baseline: 1.2031x; 1.0337x over previous
#include <cuda_runtime.h>
#include <cuda_fp16.h>
#include <cstdint>

#define N_ROWS 524288
#define DIM 256
#define NSEG 8192
#define M_TILES 4096      // 128-row M tiles
#define GRID_A 148

// ---------------- scratch (device globals) ----------------------------------
__device__ float    g_seg_sum[NSEG * DIM];
__device__ unsigned g_seg_max[NSEG * DIM];
__device__ int      g_rowstart[NSEG + 1];
__device__ __half   g_W1h[DIM * DIM];
__device__ __half   g_Wph[DIM * 2 * DIM];

// ---------------- helpers ----------------------------------------------------
__device__ __forceinline__ uint32_t smem_u32(const void* p) {
    uint32_t a;
    asm("{ .reg .u64 t; cvta.to.shared.u64 t, %1; cvt.u32.u64 %0, t; }" : "=r"(a) : "l"(p));
    return a;
}
__device__ __forceinline__ void ldmat_x4(uint32_t r[4], uint32_t addr) {
    asm volatile("ldmatrix.sync.aligned.m8n8.x4.shared.b16 {%0,%1,%2,%3}, [%4];"
                 : "=r"(r[0]), "=r"(r[1]), "=r"(r[2]), "=r"(r[3]) : "r"(addr));
}
__device__ __forceinline__ void mma16816(float d[4], const uint32_t a[4],
                                         uint32_t b0, uint32_t b1) {
    asm volatile("mma.sync.aligned.m16n8k16.row.col.f32.f16.f16.f32 "
                 "{%0,%1,%2,%3}, {%4,%5,%6,%7}, {%8,%9}, {%0,%1,%2,%3};"
                 : "+f"(d[0]), "+f"(d[1]), "+f"(d[2]), "+f"(d[3])
                 : "r"(a[0]), "r"(a[1]), "r"(a[2]), "r"(a[3]), "r"(b0), "r"(b1));
}
__device__ __forceinline__ void sts8(uint32_t addr, uint32_t u0, uint32_t u1) {
    asm volatile("st.shared.v2.b32 [%0], {%1,%2};" :: "r"(addr), "r"(u0), "r"(u1) : "memory");
}
__device__ __forceinline__ void sts16(uint32_t addr, uint4 v) {
    asm volatile("st.shared.v4.b32 [%0], {%1,%2,%3,%4};"
                 :: "r"(addr), "r"(v.x), "r"(v.y), "r"(v.z), "r"(v.w) : "memory");
}
__device__ __forceinline__ void prefetch_l2(const void* p) {
    asm volatile("prefetch.global.L2 [%0];" :: "l"(p));
}
__device__ __forceinline__ unsigned enc_f(float f) {
    unsigned i = __float_as_uint(f);
    return (i & 0x80000000u) ? ~i : (i | 0x80000000u);
}
__device__ __forceinline__ float dec_f(unsigned u) {
    return __uint_as_float((u & 0x80000000u) ? (u & 0x7FFFFFFFu) : ~u);
}
#define RSWZ(row) (((uint32_t)((row) & 7)) << 4)

// ---------------- kernel A smem layout (512B rows, swizzled) ----------------
#define OFF_W    0u          // 256 rows x 512B = 131072
#define OFF_A    131072u     // 128 rows x 512B = 65536
#define OFF_BIAS 196608u     // 1024
#define OFF_SEG  197632u     // 512
#define SMEM_A_BYTES 198144

// ---------------- proj smem layout (tile M=32) --------------------------------
#define P_OFF_B    0u        // Wp chunk: 256 x 128B = 32768
#define P_OFF_XA   32768u    // xpool chunk: 32 x 128B = 4096
#define P_OFF_OUT  36864u    // 32 x 260 x 4 = 33280
#define P_OFF_CNT  70144u    // 128
#define P_OFF_INV  70272u    // 128
#define P_OFF_BP   70400u    // 1024
#define SMEM_P_BYTES 71424
#define OUT_LD 260

// ---------------- prep: init + wconv + rowstart (role blocks) ----------------
__global__ void prep_kernel(const float* __restrict__ W1,
                            const float* __restrict__ Wp,
                            const int*   __restrict__ bidx)
{
    const int b = blockIdx.x;
    const int t = threadIdx.x;

    if (b < 8192) {                       // init
        int i = b * 256 + t;
        g_seg_sum[i] = 0.0f;
        g_seg_max[i] = 0u;
    } else if (b < 8192 + 384) {          // wconv
        int i = (b - 8192) * 256 + t;
        if (i < 32768) {
            float2 f = ((const float2*)W1)[i];
            ((__half2*)g_W1h)[i] = __floats2half2_rn(f.x, f.y);
        } else {
            int j = i - 32768;
            float2 f = ((const float2*)Wp)[j];
            ((__half2*)g_Wph)[j] = __floats2half2_rn(f.x, f.y);
        }
    } else {                              // rowstart
        int s = (b - 8192 - 384) * 256 + t;
        int lo = 0, hi = N_ROWS;
        while (lo < hi) {
            int mid = (lo + hi) >> 1;
            if (__ldg(&bidx[mid]) < s) lo = mid + 1; else hi = mid;
        }
        g_rowstart[s] = lo;
        if (s == 0) g_rowstart[NSEG] = N_ROWS;
    }
}

// convert one batch of 8 float4 (fp32) to fp16 smem, batch b covers
// idx = b*2048 + j*256 + t over the 8192-float4 tile (row = idx>>6, q = idx&63)
__device__ __forceinline__ void cvt_store_batch(uint32_t sb, int bch, int t,
                                                const float4 pf[8]) {
#pragma unroll
    for (int j = 0; j < 8; j++) {
        int idx = bch * 2048 + j * 256 + t;
        int r = idx >> 6, q = idx & 63;
        __half2 h0 = __floats2half2_rn(pf[j].x, pf[j].y);
        __half2 h1 = __floats2half2_rn(pf[j].z, pf[j].w);
        uint32_t addr = (sb + OFF_A + (uint32_t)r * 512u + (uint32_t)q * 8u) ^ RSWZ(r);
        sts8(addr, *(uint32_t*)&h0, *(uint32_t*)&h1);
    }
}

// ---------------- kernel A: HMMA GEMM + shuffle segmented reduce -------------
// 256 thr = 8 warps (2M x 4N); warp tile 64x64; fp32 x converted in-kernel;
// next tile L2-prefetched at mainloop start.
__global__ void __launch_bounds__(256, 1) gemm_pool_mma(
    const float* __restrict__ x,
    const int*   __restrict__ bidx,
    const float* __restrict__ b1)
{
    extern __shared__ char smem[];
    const uint32_t sb = smem_u32(smem);
    const int t    = threadIdx.x;
    const int w    = t >> 5;
    const int lane = t & 31;
    const int wm   = w >> 2;          // 0..1 (64-row band)
    const int wn   = w & 3;           // 0..3 (64-col band)

    float* bias_s = (float*)(smem + OFF_BIAS);
    int*   seg_s  = (int*)(smem + OFF_SEG);

    bias_s[t] = b1[t];

    // ---- first tile: load fp32 -> convert -> smem (4 batches, pipelined) ----
    {
        const int rowbase = blockIdx.x * 128;
        const float4* xb4 = (const float4*)(x + (size_t)rowbase * DIM);
        float4 pf[8];
#pragma unroll
        for (int j = 0; j < 8; j++) pf[j] = xb4[j * 256 + t];
#pragma unroll
        for (int bch = 0; bch < 4; bch++) {
            float4 nx[8];
            if (bch < 3) {
#pragma unroll
                for (int j = 0; j < 8; j++) nx[j] = xb4[(bch + 1) * 2048 + j * 256 + t];
            }
            cvt_store_batch(sb, bch, t, pf);
            if (bch < 3) {
#pragma unroll
                for (int j = 0; j < 8; j++) pf[j] = nx[j];
            }
        }
        if (t < 128) seg_s[t] = bidx[rowbase + t];
    }

    // ---- W1 fp16 -> SMEM [n][k] 512B rows, swizzled (once per CTA) ----
    {
        const uint4* wsrc = (const uint4*)g_W1h;
#pragma unroll
        for (int j = 0; j < 32; j++) {
            int idx = j * 256 + t;
            int row = idx >> 5, q = idx & 31;
            uint32_t addr = (sb + OFF_W + (uint32_t)row * 512u + (uint32_t)q * 16u) ^ RSWZ(row);
            sts16(addr, wsrc[idx]);
        }
    }
    __syncthreads();

    const uint32_t xmask  = RSWZ(lane);
    const uint32_t a_base = sb + OFF_A + (uint32_t)(wm * 64 + (lane & 15)) * 512u + (uint32_t)(lane >> 4) * 16u;
    const uint32_t b_base = sb + OFF_W + (uint32_t)(wn * 64 + (lane & 15)) * 512u + (uint32_t)(lane >> 4) * 16u;
    const int colbase = wn * 64 + 2 * (lane & 3);

    for (int tile = blockIdx.x; tile < M_TILES; tile += GRID_A) {
        const int  ntile = tile + GRID_A;
        const bool more  = ntile < M_TILES;
        const float4* xn4 = (const float4*)(x + (size_t)ntile * 128 * DIM);

        // ---- L2 prefetch next tile (4 x 128B lines per thread; no regs held) ----
        if (more) {
            const char* pb = (const char*)xn4;
#pragma unroll
            for (int i = 0; i < 4; i++)
                prefetch_l2(pb + (size_t)(i * 256 + t) * 128);
        }

        // ---- HMMA mainloop: K = 256 in 16 steps; warp tile 64x64 ----
        float acc[4][8][4];
#pragma unroll
        for (int mi = 0; mi < 4; mi++)
#pragma unroll
            for (int ni = 0; ni < 8; ni++)
#pragma unroll
                for (int d = 0; d < 4; d++) acc[mi][ni][d] = 0.0f;

#pragma unroll 2
        for (int ks = 0; ks < 16; ks++) {
            const uint32_t koff = (uint32_t)ks * 32u;
            uint32_t af[4][4];
#pragma unroll
            for (int mi = 0; mi < 4; mi++)
                ldmat_x4(af[mi], (a_base + (uint32_t)mi * 8192u + koff) ^ xmask);
#pragma unroll
            for (int p = 0; p < 4; p++) {
                uint32_t bf[4];
                ldmat_x4(bf, (b_base + (uint32_t)p * 8192u + koff) ^ xmask);
#pragma unroll
                for (int mi = 0; mi < 4; mi++) {
                    mma16816(acc[mi][2 * p],     af[mi], bf[0], bf[2]);
                    mma16816(acc[mi][2 * p + 1], af[mi], bf[1], bf[3]);
                }
            }
        }
        __syncthreads();   // all warps done reading A-smem

        // ---- prefetch batch0 of next x tile (fp32) into regs ----
        float4 pf[8];
        int segnext = 0;
        if (more) {
#pragma unroll
            for (int j = 0; j < 8; j++) pf[j] = xn4[j * 256 + t];
            if (t < 128) segnext = bidx[ntile * 128 + t];
        }

        // ---- barrier-free epilogue: bias + shuffle segmented reduce ----
        {
            float bb[16];
#pragma unroll
            for (int i = 0; i < 16; i++) bb[i] = bias_s[colbase + (i >> 1) * 8 + (i & 1)];
#pragma unroll
            for (int mi = 0; mi < 4; mi++)
#pragma unroll
                for (int ni = 0; ni < 8; ni++)
#pragma unroll
                    for (int d = 0; d < 4; d++)
                        acc[mi][ni][d] += bb[ni * 2 + (d & 1)];

            float ps[16], pm[16];
            int pseg = -1;

#pragma unroll
            for (int b = 0; b < 8; b++) {
                const int mi = b >> 1, rh = b & 1;
                const int rb = wm * 64 + mi * 16 + rh * 8;
                const int seg0 = seg_s[rb];
                const int seg7 = seg_s[rb + 7];

                float v[16];
#pragma unroll
                for (int ni = 0; ni < 8; ni++) {
                    v[ni * 2]     = acc[mi][ni][2 * rh];
                    v[ni * 2 + 1] = acc[mi][ni][2 * rh + 1];
                }

                if (seg0 == seg7) {
                    if (pseg == seg0) {
#pragma unroll
                        for (int i = 0; i < 16; i++) {
                            ps[i] += v[i];
                            pm[i] = fmaxf(pm[i], v[i]);
                        }
                    } else {
                        if (pseg >= 0) {
#pragma unroll
                            for (int r = 4; r <= 16; r <<= 1)
#pragma unroll
                                for (int i = 0; i < 16; i++) {
                                    ps[i] += __shfl_xor_sync(0xFFFFFFFFu, ps[i], r);
                                    pm[i] = fmaxf(pm[i], __shfl_xor_sync(0xFFFFFFFFu, pm[i], r));
                                }
                            unsigned gb = (unsigned)pseg * DIM + colbase;
                            if (lane < 4) {
#pragma unroll
                                for (int i = 0; i < 16; i++)
                                    atomicAdd(&g_seg_sum[gb + (i >> 1) * 8 + (i & 1)], ps[i]);
                            } else if (lane < 8) {
#pragma unroll
                                for (int i = 0; i < 16; i++)
                                    atomicMax(&g_seg_max[gb + (i >> 1) * 8 + (i & 1)], enc_f(pm[i]));
                            }
                        }
#pragma unroll
                        for (int i = 0; i < 16; i++) { ps[i] = v[i]; pm[i] = v[i]; }
                        pseg = seg0;
                    }
                } else {
                    const int myseg = seg_s[rb + (lane >> 2)];
                    unsigned gb = (unsigned)myseg * DIM + colbase;
#pragma unroll
                    for (int i = 0; i < 16; i++) {
                        atomicAdd(&g_seg_sum[gb + (i >> 1) * 8 + (i & 1)], v[i]);
                        atomicMax(&g_seg_max[gb + (i >> 1) * 8 + (i & 1)], enc_f(v[i]));
                    }
                }
            }
            if (pseg >= 0) {
#pragma unroll
                for (int r = 4; r <= 16; r <<= 1)
#pragma unroll
                    for (int i = 0; i < 16; i++) {
                        ps[i] += __shfl_xor_sync(0xFFFFFFFFu, ps[i], r);
                        pm[i] = fmaxf(pm[i], __shfl_xor_sync(0xFFFFFFFFu, pm[i], r));
                    }
                unsigned gb = (unsigned)pseg * DIM + colbase;
                if (lane < 4) {
#pragma unroll
                    for (int i = 0; i < 16; i++)
                        atomicAdd(&g_seg_sum[gb + (i >> 1) * 8 + (i & 1)], ps[i]);
                } else if (lane < 8) {
#pragma unroll
                    for (int i = 0; i < 16; i++)
                        atomicMax(&g_seg_max[gb + (i >> 1) * 8 + (i & 1)], enc_f(pm[i]));
                }
            }
        }

        // ---- remaining batches: load(b+1) then convert/store(b); acc dead ----
        if (more) {
#pragma unroll
            for (int bch = 0; bch < 4; bch++) {
                float4 nx[8];
                if (bch < 3) {
#pragma unroll
                    for (int j = 0; j < 8; j++) nx[j] = xn4[(bch + 1) * 2048 + j * 256 + t];
                }
                cvt_store_batch(sb, bch, t, pf);
                if (bch < 3) {
#pragma unroll
                    for (int j = 0; j < 8; j++) pf[j] = nx[j];
                }
            }
        }
        __syncthreads();   // A(next) visible; all seg_s reads done
        if (more && t < 128) seg_s[t] = segnext;   // ordered before next epilogue by next post-mainloop sync
    }
}

// ---------------- proj: HMMA fp16 GEMM + fused MLP-4 scatter ------------------
__global__ void __launch_bounds__(256, 2) proj_scatter(
    const int*   __restrict__ bidx,
    const float* __restrict__ bp,
    float4*      __restrict__ out4)
{
    extern __shared__ char smem[];
    const uint32_t sb = smem_u32(smem);
    const int t    = threadIdx.x;
    const int w    = t >> 5;
    const int lane = t & 31;
    const int wn   = w;
    const int tileM = blockIdx.x * 32;

    int*   cnt_s  = (int*)(smem + P_OFF_CNT);
    float* invc_s = (float*)(smem + P_OFF_INV);
    float* bp_s   = (float*)(smem + P_OFF_BP);
    float* outs   = (float*)(smem + P_OFF_OUT);

    if (t < 32) {
        int cn = g_rowstart[tileM + t + 1] - g_rowstart[tileM + t];
        cnt_s[t]  = cn;
        invc_s[t] = 1.0f / (float)max(cn, 1);
    }
    bp_s[t] = bp[t];

    const uint32_t xmask  = RSWZ(lane);
    const uint32_t a_base = sb + P_OFF_XA + (uint32_t)(lane & 15) * 128u + (uint32_t)(lane >> 4) * 16u;
    const uint32_t b_base = sb + P_OFF_B  + (uint32_t)(wn * 32 + (lane & 15)) * 128u + (uint32_t)(lane >> 4) * 16u;

    float acc[2][4][4];
#pragma unroll
    for (int mi = 0; mi < 2; mi++)
#pragma unroll
        for (int ni = 0; ni < 4; ni++)
#pragma unroll
            for (int d = 0; d < 4; d++) acc[mi][ni][d] = 0.0f;

#pragma unroll 1
    for (int kc = 0; kc < 8; kc++) {
        // L2 prefetch next chunk of xpool source (8 KB -> 64 lines / 256 thr)
        if (kc < 7) {
            int nkc = kc + 1;
            if ((t >> 6) == 0) {
                const char* p = (nkc < 4)
                    ? (const char*)&g_seg_sum[(size_t)(tileM + (t >> 1)) * DIM + nkc * 64 + (t & 1) * 32]
                    : (const char*)&g_seg_max[(size_t)(tileM + (t >> 1)) * DIM + (nkc - 4) * 64 + (t & 1) * 32];
                prefetch_l2(p);
            }
        }
        __syncthreads();

#pragma unroll
        for (int i = 0; i < 2; i++) {
            int idx = i * 256 + t;
            int row = idx >> 4, q = idx & 15;
            float4 va;
            if (kc < 4) {
                va = *(const float4*)&g_seg_sum[(size_t)(tileM + row) * DIM + kc * 64 + q * 4];
                float iv = invc_s[row];
                va.x *= iv; va.y *= iv; va.z *= iv; va.w *= iv;
            } else {
                uint4 u = *(const uint4*)&g_seg_max[(size_t)(tileM + row) * DIM + (kc - 4) * 64 + q * 4];
                if (cnt_s[row] > 0) {
                    va.x = dec_f(u.x); va.y = dec_f(u.y); va.z = dec_f(u.z); va.w = dec_f(u.w);
                } else {
                    va.x = va.y = va.z = va.w = 0.0f;
                }
            }
            __half2 h0 = __floats2half2_rn(va.x, va.y);
            __half2 h1 = __floats2half2_rn(va.z, va.w);
            uint32_t addr = (sb + P_OFF_XA + (uint32_t)row * 128u + (uint32_t)q * 8u) ^ RSWZ(row);
            sts8(addr, *(uint32_t*)&h0, *(uint32_t*)&h1);
        }
#pragma unroll
        for (int i = 0; i < 8; i++) {
            int idx = i * 256 + t;
            int row = idx >> 3, q = idx & 7;
            uint4 v = ((const uint4*)g_Wph)[row * 64 + kc * 8 + q];
            uint32_t addr = (sb + P_OFF_B + (uint32_t)row * 128u + (uint32_t)q * 16u) ^ RSWZ(row);
            sts16(addr, v);
        }
        __syncthreads();

#pragma unroll
        for (int ks = 0; ks < 4; ks++) {
            const uint32_t koff = (uint32_t)ks * 32u;
            uint32_t a0[4], a1[4];
            ldmat_x4(a0, (a_base + koff) ^ xmask);
            ldmat_x4(a1, (a_base + 16u * 128u + koff) ^ xmask);
#pragma unroll
            for (int p = 0; p < 2; p++) {
                uint32_t bf[4];
                ldmat_x4(bf, (b_base + (uint32_t)p * 2048u + koff) ^ xmask);
                mma16816(acc[0][2 * p],     a0, bf[0], bf[2]);
                mma16816(acc[0][2 * p + 1], a0, bf[1], bf[3]);
                mma16816(acc[1][2 * p],     a1, bf[0], bf[2]);
                mma16816(acc[1][2 * p + 1], a1, bf[1], bf[3]);
            }
        }
    }

    {
        const int r0 = lane >> 2;
        const int c0 = wn * 32 + 2 * (lane & 3);
#pragma unroll
        for (int mi = 0; mi < 2; mi++)
#pragma unroll
            for (int ni = 0; ni < 4; ni++) {
                int col = c0 + ni * 8;
                float bb0 = bp_s[col], bb1 = bp_s[col + 1];
                int rr = r0 + mi * 16;
                outs[rr * OUT_LD + col]           = acc[mi][ni][0] + bb0;
                outs[rr * OUT_LD + col + 1]       = acc[mi][ni][1] + bb1;
                outs[(rr + 8) * OUT_LD + col]     = acc[mi][ni][2] + bb0;
                outs[(rr + 8) * OUT_LD + col + 1] = acc[mi][ni][3] + bb1;
            }
    }
    __syncthreads();

    const int rstart = g_rowstart[tileM];
    const int rend   = g_rowstart[tileM + 32];
    const int cq     = t & 63;
    int r = rstart + (t >> 6);
    for (; r + 12 < rend; r += 16) {
        int s0 = __ldg(&bidx[r])      - tileM;
        int s1 = __ldg(&bidx[r +  4]) - tileM;
        int s2 = __ldg(&bidx[r +  8]) - tileM;
        int s3 = __ldg(&bidx[r + 12]) - tileM;
        float4 v0 = *(const float4*)&outs[s0 * OUT_LD + cq * 4];
        float4 v1 = *(const float4*)&outs[s1 * OUT_LD + cq * 4];
        float4 v2 = *(const float4*)&outs[s2 * OUT_LD + cq * 4];
        float4 v3 = *(const float4*)&outs[s3 * OUT_LD + cq * 4];
        out4[(size_t)r * 64 + cq]        = v0;
        out4[(size_t)(r +  4) * 64 + cq] = v1;
        out4[(size_t)(r +  8) * 64 + cq] = v2;
        out4[(size_t)(r + 12) * 64 + cq] = v3;
    }
    for (; r < rend; r += 4) {
        int s0 = __ldg(&bidx[r]) - tileM;
        out4[(size_t)r * 64 + cq] = *(const float4*)&outs[s0 * OUT_LD + cq * 4];
    }
}

// ---------------- launch -----------------------------------------------------
extern "C" void kernel_launch(void* const* d_in, const int* in_sizes, int n_in,
                              void* d_out, int out_size) {
    const float* x    = (const float*)d_in[0];
    const int*   bidx = (const int*)  d_in[1];
    const float* W1   = (const float*)d_in[2];
    const float* b1   = (const float*)d_in[3];
    const float* Wp   = (const float*)d_in[4];
    const float* bp   = (const float*)d_in[5];

    cudaFuncSetAttribute(gemm_pool_mma, cudaFuncAttributeMaxDynamicSharedMemorySize,
                         SMEM_A_BYTES);
    cudaFuncSetAttribute(proj_scatter, cudaFuncAttributeMaxDynamicSharedMemorySize,
                         SMEM_P_BYTES);

    prep_kernel<<<8192 + 384 + 32, 256>>>(W1, Wp, bidx);

    gemm_pool_mma<<<GRID_A, 256, SMEM_A_BYTES>>>(x, bidx, b1);

    proj_scatter<<<NSEG / 32, 256, SMEM_P_BYTES>>>(bidx, bp, (float4*)d_out);
}

// round 15
// speedup vs baseline: 1.2163x; 1.0110x over previous
#include <cuda_runtime.h>
#include <cuda_fp16.h>
#include <cstdint>

#define N_ROWS 524288
#define DIM 256
#define NSEG 8192
#define M_TILES 4096      // 128-row M tiles
#define GRID_A 148

// ---------------- scratch (device globals) ----------------------------------
__device__ float    g_seg_sum[NSEG * DIM];
__device__ unsigned g_seg_max[NSEG * DIM];
__device__ int      g_rowstart[NSEG + 1];
__device__ __half   g_W1h[DIM * DIM];
__device__ __half   g_Wph[DIM * 2 * DIM];

// ---------------- helpers ----------------------------------------------------
__device__ __forceinline__ uint32_t smem_u32(const void* p) {
    uint32_t a;
    asm("{ .reg .u64 t; cvta.to.shared.u64 t, %1; cvt.u32.u64 %0, t; }" : "=r"(a) : "l"(p));
    return a;
}
__device__ __forceinline__ void ldmat_x4(uint32_t r[4], uint32_t addr) {
    asm volatile("ldmatrix.sync.aligned.m8n8.x4.shared.b16 {%0,%1,%2,%3}, [%4];"
                 : "=r"(r[0]), "=r"(r[1]), "=r"(r[2]), "=r"(r[3]) : "r"(addr));
}
__device__ __forceinline__ void mma16816(float d[4], const uint32_t a[4],
                                         uint32_t b0, uint32_t b1) {
    asm volatile("mma.sync.aligned.m16n8k16.row.col.f32.f16.f16.f32 "
                 "{%0,%1,%2,%3}, {%4,%5,%6,%7}, {%8,%9}, {%0,%1,%2,%3};"
                 : "+f"(d[0]), "+f"(d[1]), "+f"(d[2]), "+f"(d[3])
                 : "r"(a[0]), "r"(a[1]), "r"(a[2]), "r"(a[3]), "r"(b0), "r"(b1));
}
__device__ __forceinline__ void sts8(uint32_t addr, uint32_t u0, uint32_t u1) {
    asm volatile("st.shared.v2.b32 [%0], {%1,%2};" :: "r"(addr), "r"(u0), "r"(u1) : "memory");
}
__device__ __forceinline__ void sts16(uint32_t addr, uint4 v) {
    asm volatile("st.shared.v4.b32 [%0], {%1,%2,%3,%4};"
                 :: "r"(addr), "r"(v.x), "r"(v.y), "r"(v.z), "r"(v.w) : "memory");
}
__device__ __forceinline__ void cpasync16(uint32_t dst, const void* src) {
    asm volatile("cp.async.cg.shared.global [%0], [%1], 16;" :: "r"(dst), "l"(src) : "memory");
}
#define CP_COMMIT() asm volatile("cp.async.commit_group;" ::: "memory")
#define CP_WAIT0()  asm volatile("cp.async.wait_group 0;"  ::: "memory")
__device__ __forceinline__ void prefetch_l2(const void* p) {
    asm volatile("prefetch.global.L2 [%0];" :: "l"(p));
}
__device__ __forceinline__ unsigned enc_f(float f) {
    unsigned i = __float_as_uint(f);
    return (i & 0x80000000u) ? ~i : (i | 0x80000000u);
}
__device__ __forceinline__ float dec_f(unsigned u) {
    return __uint_as_float((u & 0x80000000u) ? (u & 0x7FFFFFFFu) : ~u);
}
#define RSWZ(row) (((uint32_t)((row) & 7)) << 4)

// ---------------- kernel A smem layout (512B rows, swizzled) ----------------
#define OFF_W    0u          // 256 rows x 512B = 131072
#define OFF_A    131072u     // 128 rows x 512B = 65536
#define OFF_BIAS 196608u     // 1024
#define OFF_SEG  197632u     // 512
#define SMEM_A_BYTES 198144

// ---------------- proj smem layout (tile M=32, double-buffered B/XA) ---------
#define P_OFF_B0   0u        // Wp chunk buf0: 32768
#define P_OFF_B1   32768u    // Wp chunk buf1: 32768
#define P_OFF_XA0  65536u    // xpool buf0: 4096
#define P_OFF_XA1  69632u    // xpool buf1: 4096
#define P_OFF_OUT  73728u    // 32 x 260 x 4 = 33280
#define P_OFF_CNT  107008u   // 128
#define P_OFF_INV  107136u   // 128
#define P_OFF_BP   107264u   // 1024
#define SMEM_P_BYTES 108288
#define OUT_LD 260

// ---------------- prep: init (vectorized) + wconv + rowstart -----------------
__global__ void prep_kernel(const float* __restrict__ W1,
                            const float* __restrict__ Wp,
                            const int*   __restrict__ bidx)
{
    const int b = blockIdx.x;
    const int t = threadIdx.x;

    if (b < 2048) {                       // init: 2048*256 uint4 per array
        int i = b * 256 + t;
        ((uint4*)g_seg_sum)[i] = make_uint4(0u, 0u, 0u, 0u);
        ((uint4*)g_seg_max)[i] = make_uint4(0u, 0u, 0u, 0u);
    } else if (b < 2048 + 384) {          // wconv
        int i = (b - 2048) * 256 + t;
        if (i < 32768) {
            float2 f = ((const float2*)W1)[i];
            ((__half2*)g_W1h)[i] = __floats2half2_rn(f.x, f.y);
        } else {
            int j = i - 32768;
            float2 f = ((const float2*)Wp)[j];
            ((__half2*)g_Wph)[j] = __floats2half2_rn(f.x, f.y);
        }
    } else {                              // rowstart
        int s = (b - 2048 - 384) * 256 + t;
        int lo = 0, hi = N_ROWS;
        while (lo < hi) {
            int mid = (lo + hi) >> 1;
            if (__ldg(&bidx[mid]) < s) lo = mid + 1; else hi = mid;
        }
        g_rowstart[s] = lo;
        if (s == 0) g_rowstart[NSEG] = N_ROWS;
    }
}

// convert one batch of 8 float4 (fp32) to fp16 smem, batch b covers
// idx = b*2048 + j*256 + t over the 8192-float4 tile (row = idx>>6, q = idx&63)
__device__ __forceinline__ void cvt_store_batch(uint32_t sb, int bch, int t,
                                                const float4 pf[8]) {
#pragma unroll
    for (int j = 0; j < 8; j++) {
        int idx = bch * 2048 + j * 256 + t;
        int r = idx >> 6, q = idx & 63;
        __half2 h0 = __floats2half2_rn(pf[j].x, pf[j].y);
        __half2 h1 = __floats2half2_rn(pf[j].z, pf[j].w);
        uint32_t addr = (sb + OFF_A + (uint32_t)r * 512u + (uint32_t)q * 8u) ^ RSWZ(r);
        sts8(addr, *(uint32_t*)&h0, *(uint32_t*)&h1);
    }
}

// ---------------- kernel A: HMMA GEMM + shuffle segmented reduce -------------
// (unchanged from best round: 8 warps 2Mx4N, warp tile 64x64, L2-prefetched
//  next tile, batch-pipelined fp32->fp16 conversion)
__global__ void __launch_bounds__(256, 1) gemm_pool_mma(
    const float* __restrict__ x,
    const int*   __restrict__ bidx,
    const float* __restrict__ b1)
{
    extern __shared__ char smem[];
    const uint32_t sb = smem_u32(smem);
    const int t    = threadIdx.x;
    const int w    = t >> 5;
    const int lane = t & 31;
    const int wm   = w >> 2;
    const int wn   = w & 3;

    float* bias_s = (float*)(smem + OFF_BIAS);
    int*   seg_s  = (int*)(smem + OFF_SEG);

    bias_s[t] = b1[t];

    {
        const int rowbase = blockIdx.x * 128;
        const float4* xb4 = (const float4*)(x + (size_t)rowbase * DIM);
        float4 pf[8];
#pragma unroll
        for (int j = 0; j < 8; j++) pf[j] = xb4[j * 256 + t];
#pragma unroll
        for (int bch = 0; bch < 4; bch++) {
            float4 nx[8];
            if (bch < 3) {
#pragma unroll
                for (int j = 0; j < 8; j++) nx[j] = xb4[(bch + 1) * 2048 + j * 256 + t];
            }
            cvt_store_batch(sb, bch, t, pf);
            if (bch < 3) {
#pragma unroll
                for (int j = 0; j < 8; j++) pf[j] = nx[j];
            }
        }
        if (t < 128) seg_s[t] = bidx[rowbase + t];
    }

    {
        const uint4* wsrc = (const uint4*)g_W1h;
#pragma unroll
        for (int j = 0; j < 32; j++) {
            int idx = j * 256 + t;
            int row = idx >> 5, q = idx & 31;
            uint32_t addr = (sb + OFF_W + (uint32_t)row * 512u + (uint32_t)q * 16u) ^ RSWZ(row);
            sts16(addr, wsrc[idx]);
        }
    }
    __syncthreads();

    const uint32_t xmask  = RSWZ(lane);
    const uint32_t a_base = sb + OFF_A + (uint32_t)(wm * 64 + (lane & 15)) * 512u + (uint32_t)(lane >> 4) * 16u;
    const uint32_t b_base = sb + OFF_W + (uint32_t)(wn * 64 + (lane & 15)) * 512u + (uint32_t)(lane >> 4) * 16u;
    const int colbase = wn * 64 + 2 * (lane & 3);

    for (int tile = blockIdx.x; tile < M_TILES; tile += GRID_A) {
        const int  ntile = tile + GRID_A;
        const bool more  = ntile < M_TILES;
        const float4* xn4 = (const float4*)(x + (size_t)ntile * 128 * DIM);

        if (more) {
            const char* pb = (const char*)xn4;
#pragma unroll
            for (int i = 0; i < 4; i++)
                prefetch_l2(pb + (size_t)(i * 256 + t) * 128);
        }

        float acc[4][8][4];
#pragma unroll
        for (int mi = 0; mi < 4; mi++)
#pragma unroll
            for (int ni = 0; ni < 8; ni++)
#pragma unroll
                for (int d = 0; d < 4; d++) acc[mi][ni][d] = 0.0f;

#pragma unroll 2
        for (int ks = 0; ks < 16; ks++) {
            const uint32_t koff = (uint32_t)ks * 32u;
            uint32_t af[4][4];
#pragma unroll
            for (int mi = 0; mi < 4; mi++)
                ldmat_x4(af[mi], (a_base + (uint32_t)mi * 8192u + koff) ^ xmask);
#pragma unroll
            for (int p = 0; p < 4; p++) {
                uint32_t bf[4];
                ldmat_x4(bf, (b_base + (uint32_t)p * 8192u + koff) ^ xmask);
#pragma unroll
                for (int mi = 0; mi < 4; mi++) {
                    mma16816(acc[mi][2 * p],     af[mi], bf[0], bf[2]);
                    mma16816(acc[mi][2 * p + 1], af[mi], bf[1], bf[3]);
                }
            }
        }
        __syncthreads();

        float4 pf[8];
        int segnext = 0;
        if (more) {
#pragma unroll
            for (int j = 0; j < 8; j++) pf[j] = xn4[j * 256 + t];
            if (t < 128) segnext = bidx[ntile * 128 + t];
        }

        {
            float bb[16];
#pragma unroll
            for (int i = 0; i < 16; i++) bb[i] = bias_s[colbase + (i >> 1) * 8 + (i & 1)];
#pragma unroll
            for (int mi = 0; mi < 4; mi++)
#pragma unroll
                for (int ni = 0; ni < 8; ni++)
#pragma unroll
                    for (int d = 0; d < 4; d++)
                        acc[mi][ni][d] += bb[ni * 2 + (d & 1)];

            float ps[16], pm[16];
            int pseg = -1;

#pragma unroll
            for (int b = 0; b < 8; b++) {
                const int mi = b >> 1, rh = b & 1;
                const int rb = wm * 64 + mi * 16 + rh * 8;
                const int seg0 = seg_s[rb];
                const int seg7 = seg_s[rb + 7];

                float v[16];
#pragma unroll
                for (int ni = 0; ni < 8; ni++) {
                    v[ni * 2]     = acc[mi][ni][2 * rh];
                    v[ni * 2 + 1] = acc[mi][ni][2 * rh + 1];
                }

                if (seg0 == seg7) {
                    if (pseg == seg0) {
#pragma unroll
                        for (int i = 0; i < 16; i++) {
                            ps[i] += v[i];
                            pm[i] = fmaxf(pm[i], v[i]);
                        }
                    } else {
                        if (pseg >= 0) {
#pragma unroll
                            for (int r = 4; r <= 16; r <<= 1)
#pragma unroll
                                for (int i = 0; i < 16; i++) {
                                    ps[i] += __shfl_xor_sync(0xFFFFFFFFu, ps[i], r);
                                    pm[i] = fmaxf(pm[i], __shfl_xor_sync(0xFFFFFFFFu, pm[i], r));
                                }
                            unsigned gb = (unsigned)pseg * DIM + colbase;
                            if (lane < 4) {
#pragma unroll
                                for (int i = 0; i < 16; i++)
                                    atomicAdd(&g_seg_sum[gb + (i >> 1) * 8 + (i & 1)], ps[i]);
                            } else if (lane < 8) {
#pragma unroll
                                for (int i = 0; i < 16; i++)
                                    atomicMax(&g_seg_max[gb + (i >> 1) * 8 + (i & 1)], enc_f(pm[i]));
                            }
                        }
#pragma unroll
                        for (int i = 0; i < 16; i++) { ps[i] = v[i]; pm[i] = v[i]; }
                        pseg = seg0;
                    }
                } else {
                    const int myseg = seg_s[rb + (lane >> 2)];
                    unsigned gb = (unsigned)myseg * DIM + colbase;
#pragma unroll
                    for (int i = 0; i < 16; i++) {
                        atomicAdd(&g_seg_sum[gb + (i >> 1) * 8 + (i & 1)], v[i]);
                        atomicMax(&g_seg_max[gb + (i >> 1) * 8 + (i & 1)], enc_f(v[i]));
                    }
                }
            }
            if (pseg >= 0) {
#pragma unroll
                for (int r = 4; r <= 16; r <<= 1)
#pragma unroll
                    for (int i = 0; i < 16; i++) {
                        ps[i] += __shfl_xor_sync(0xFFFFFFFFu, ps[i], r);
                        pm[i] = fmaxf(pm[i], __shfl_xor_sync(0xFFFFFFFFu, pm[i], r));
                    }
                unsigned gb = (unsigned)pseg * DIM + colbase;
                if (lane < 4) {
#pragma unroll
                    for (int i = 0; i < 16; i++)
                        atomicAdd(&g_seg_sum[gb + (i >> 1) * 8 + (i & 1)], ps[i]);
                } else if (lane < 8) {
#pragma unroll
                    for (int i = 0; i < 16; i++)
                        atomicMax(&g_seg_max[gb + (i >> 1) * 8 + (i & 1)], enc_f(pm[i]));
                }
            }
        }

        if (more) {
#pragma unroll
            for (int bch = 0; bch < 4; bch++) {
                float4 nx[8];
                if (bch < 3) {
#pragma unroll
                    for (int j = 0; j < 8; j++) nx[j] = xn4[(bch + 1) * 2048 + j * 256 + t];
                }
                cvt_store_batch(sb, bch, t, pf);
                if (bch < 3) {
#pragma unroll
                    for (int j = 0; j < 8; j++) pf[j] = nx[j];
                }
            }
        }
        __syncthreads();
        if (more && t < 128) seg_s[t] = segnext;
    }
}

// issue cp.async for Wp chunk kc into buffer buf (2048 16B chunks / 256 thr)
__device__ __forceinline__ void issue_wp(uint32_t sb, int kc, int buf, int t) {
    const uint32_t base = sb + (buf ? P_OFF_B1 : P_OFF_B0);
#pragma unroll
    for (int i = 0; i < 8; i++) {
        int idx = i * 256 + t;
        int row = idx >> 3, q = idx & 7;
        uint32_t dst = (base + (uint32_t)row * 128u + (uint32_t)q * 16u) ^ RSWZ(row);
        cpasync16(dst, g_Wph + (size_t)row * 512 + kc * 64 + q * 8);
    }
}

// ---------------- proj: HMMA fp16 GEMM (cp.async double-buffered Wp) ---------
// 256 CTAs x 256 thr (2/SM); tile M=32, N=256, K=512 in 8 chunks; fused scatter.
__global__ void __launch_bounds__(256, 2) proj_scatter(
    const int*   __restrict__ bidx,
    const float* __restrict__ bp,
    float4*      __restrict__ out4)
{
    extern __shared__ char smem[];
    const uint32_t sb = smem_u32(smem);
    const int t    = threadIdx.x;
    const int w    = t >> 5;
    const int lane = t & 31;
    const int wn   = w;
    const int tileM = blockIdx.x * 32;

    int*   cnt_s  = (int*)(smem + P_OFF_CNT);
    float* invc_s = (float*)(smem + P_OFF_INV);
    float* bp_s   = (float*)(smem + P_OFF_BP);
    float* outs   = (float*)(smem + P_OFF_OUT);

    if (t < 32) {
        int cn = g_rowstart[tileM + t + 1] - g_rowstart[tileM + t];
        cnt_s[t]  = cn;
        invc_s[t] = 1.0f / (float)max(cn, 1);
    }
    bp_s[t] = bp[t];

    // prologue: Wp chunk0 -> buf0
    issue_wp(sb, 0, 0, t);
    CP_COMMIT();
    __syncthreads();   // cnt/inv/bp visible before first convert

    const uint32_t xmask   = RSWZ(lane);
    const uint32_t a_base0 = sb + P_OFF_XA0 + (uint32_t)(lane & 15) * 128u + (uint32_t)(lane >> 4) * 16u;
    const uint32_t b_base0 = sb + P_OFF_B0  + (uint32_t)(wn * 32 + (lane & 15)) * 128u + (uint32_t)(lane >> 4) * 16u;

    float acc[2][4][4];
#pragma unroll
    for (int mi = 0; mi < 2; mi++)
#pragma unroll
        for (int ni = 0; ni < 4; ni++)
#pragma unroll
            for (int d = 0; d < 4; d++) acc[mi][ni][d] = 0.0f;

#pragma unroll 1
    for (int kc = 0; kc < 8; kc++) {
        const int bf_sel = kc & 1;
        const uint32_t xa_dst = sb + (bf_sel ? P_OFF_XA1 : P_OFF_XA0);

        // convert xpool chunk kc -> XA[bf_sel] (prior readers fenced by sync(kc-1))
#pragma unroll
        for (int i = 0; i < 2; i++) {
            int idx = i * 256 + t;
            int row = idx >> 4, q = idx & 15;
            float4 va;
            if (kc < 4) {
                va = *(const float4*)&g_seg_sum[(size_t)(tileM + row) * DIM + kc * 64 + q * 4];
                float iv = invc_s[row];
                va.x *= iv; va.y *= iv; va.z *= iv; va.w *= iv;
            } else {
                uint4 u = *(const uint4*)&g_seg_max[(size_t)(tileM + row) * DIM + (kc - 4) * 64 + q * 4];
                if (cnt_s[row] > 0) {
                    va.x = dec_f(u.x); va.y = dec_f(u.y); va.z = dec_f(u.z); va.w = dec_f(u.w);
                } else {
                    va.x = va.y = va.z = va.w = 0.0f;
                }
            }
            __half2 h0 = __floats2half2_rn(va.x, va.y);
            __half2 h1 = __floats2half2_rn(va.z, va.w);
            uint32_t addr = (xa_dst + (uint32_t)row * 128u + (uint32_t)q * 8u) ^ RSWZ(row);
            sts8(addr, *(uint32_t*)&h0, *(uint32_t*)&h1);
        }

        CP_WAIT0();        // B[bf_sel] (issued last iteration) landed
        __syncthreads();   // all: XA/B stores visible; MMA(kc-1) complete

        // issue next Wp chunk into the buffer MMA(kc-1) just finished reading
        if (kc < 7) {
            issue_wp(sb, kc + 1, (kc + 1) & 1, t);
            CP_COMMIT();
        }

        // MMA on chunk kc
        const uint32_t a_base = a_base0 + (uint32_t)bf_sel * 4096u;
        const uint32_t b_base = b_base0 + (uint32_t)bf_sel * 32768u;
#pragma unroll
        for (int ks = 0; ks < 4; ks++) {
            const uint32_t koff = (uint32_t)ks * 32u;
            uint32_t a0[4], a1[4];
            ldmat_x4(a0, (a_base + koff) ^ xmask);
            ldmat_x4(a1, (a_base + 16u * 128u + koff) ^ xmask);
#pragma unroll
            for (int p = 0; p < 2; p++) {
                uint32_t bfr[4];
                ldmat_x4(bfr, (b_base + (uint32_t)p * 2048u + koff) ^ xmask);
                mma16816(acc[0][2 * p],     a0, bfr[0], bfr[2]);
                mma16816(acc[0][2 * p + 1], a0, bfr[1], bfr[3]);
                mma16816(acc[1][2 * p],     a1, bfr[0], bfr[2]);
                mma16816(acc[1][2 * p + 1], a1, bfr[1], bfr[3]);
            }
        }
    }

    // ---- stage out tile [32 x 256] fp32 (+bias) ----
    {
        const int r0 = lane >> 2;
        const int c0 = wn * 32 + 2 * (lane & 3);
#pragma unroll
        for (int mi = 0; mi < 2; mi++)
#pragma unroll
            for (int ni = 0; ni < 4; ni++) {
                int col = c0 + ni * 8;
                float bb0 = bp_s[col], bb1 = bp_s[col + 1];
                int rr = r0 + mi * 16;
                outs[rr * OUT_LD + col]           = acc[mi][ni][0] + bb0;
                outs[rr * OUT_LD + col + 1]       = acc[mi][ni][1] + bb1;
                outs[(rr + 8) * OUT_LD + col]     = acc[mi][ni][2] + bb0;
                outs[(rr + 8) * OUT_LD + col + 1] = acc[mi][ni][3] + bb1;
            }
    }
    __syncthreads();

    // ---- scatter rows [rowstart(tileM), rowstart(tileM+32)) with MLP=4 ----
    const int rstart = g_rowstart[tileM];
    const int rend   = g_rowstart[tileM + 32];
    const int cq     = t & 63;
    int r = rstart + (t >> 6);
    for (; r + 12 < rend; r += 16) {
        int s0 = __ldg(&bidx[r])      - tileM;
        int s1 = __ldg(&bidx[r +  4]) - tileM;
        int s2 = __ldg(&bidx[r +  8]) - tileM;
        int s3 = __ldg(&bidx[r + 12]) - tileM;
        float4 v0 = *(const float4*)&outs[s0 * OUT_LD + cq * 4];
        float4 v1 = *(const float4*)&outs[s1 * OUT_LD + cq * 4];
        float4 v2 = *(const float4*)&outs[s2 * OUT_LD + cq * 4];
        float4 v3 = *(const float4*)&outs[s3 * OUT_LD + cq * 4];
        out4[(size_t)r * 64 + cq]        = v0;
        out4[(size_t)(r +  4) * 64 + cq] = v1;
        out4[(size_t)(r +  8) * 64 + cq] = v2;
        out4[(size_t)(r + 12) * 64 + cq] = v3;
    }
    for (; r < rend; r += 4) {
        int s0 = __ldg(&bidx[r]) - tileM;
        out4[(size_t)r * 64 + cq] = *(const float4*)&outs[s0 * OUT_LD + cq * 4];
    }
}

// ---------------- launch -----------------------------------------------------
extern "C" void kernel_launch(void* const* d_in, const int* in_sizes, int n_in,
                              void* d_out, int out_size) {
    const float* x    = (const float*)d_in[0];
    const int*   bidx = (const int*)  d_in[1];
    const float* W1   = (const float*)d_in[2];
    const float* b1   = (const float*)d_in[3];
    const float* Wp   = (const float*)d_in[4];
    const float* bp   = (const float*)d_in[5];

    cudaFuncSetAttribute(gemm_pool_mma, cudaFuncAttributeMaxDynamicSharedMemorySize,
                         SMEM_A_BYTES);
    cudaFuncSetAttribute(proj_scatter, cudaFuncAttributeMaxDynamicSharedMemorySize,
                         SMEM_P_BYTES);

    prep_kernel<<<2048 + 384 + 32, 256>>>(W1, Wp, bidx);

    gemm_pool_mma<<<GRID_A, 256, SMEM_A_BYTES>>>(x, bidx, b1);

    proj_scatter<<<NSEG / 32, 256, SMEM_P_BYTES>>>(bidx, bp, (float4*)d_out);
}

// round 16
// speedup vs baseline: 1.2704x; 1.0444x over previous
#include <cuda_runtime.h>
#include <cuda_fp16.h>
#include <cstdint>

#define N_ROWS 524288
#define DIM 256
#define NSEG 8192
#define M_TILES 4096      // 128-row M tiles
#define GRID_A 148

// ---------------- scratch (device globals) ----------------------------------
__device__ float    g_seg_sum[NSEG * DIM];
__device__ unsigned g_seg_max[NSEG * DIM];
__device__ int      g_rowstart[NSEG + 1];
__device__ __half   g_W1h[DIM * DIM];
__device__ __half   g_Wph[DIM * 2 * DIM];

// ---------------- helpers ----------------------------------------------------
__device__ __forceinline__ uint32_t smem_u32(const void* p) {
    uint32_t a;
    asm("{ .reg .u64 t; cvta.to.shared.u64 t, %1; cvt.u32.u64 %0, t; }" : "=r"(a) : "l"(p));
    return a;
}
__device__ __forceinline__ void ldmat_x4(uint32_t r[4], uint32_t addr) {
    asm volatile("ldmatrix.sync.aligned.m8n8.x4.shared.b16 {%0,%1,%2,%3}, [%4];"
                 : "=r"(r[0]), "=r"(r[1]), "=r"(r[2]), "=r"(r[3]) : "r"(addr));
}
__device__ __forceinline__ void mma16816(float d[4], const uint32_t a[4],
                                         uint32_t b0, uint32_t b1) {
    asm volatile("mma.sync.aligned.m16n8k16.row.col.f32.f16.f16.f32 "
                 "{%0,%1,%2,%3}, {%4,%5,%6,%7}, {%8,%9}, {%0,%1,%2,%3};"
                 : "+f"(d[0]), "+f"(d[1]), "+f"(d[2]), "+f"(d[3])
                 : "r"(a[0]), "r"(a[1]), "r"(a[2]), "r"(a[3]), "r"(b0), "r"(b1));
}
__device__ __forceinline__ void sts8(uint32_t addr, uint32_t u0, uint32_t u1) {
    asm volatile("st.shared.v2.b32 [%0], {%1,%2};" :: "r"(addr), "r"(u0), "r"(u1) : "memory");
}
__device__ __forceinline__ void sts16(uint32_t addr, uint4 v) {
    asm volatile("st.shared.v4.b32 [%0], {%1,%2,%3,%4};"
                 :: "r"(addr), "r"(v.x), "r"(v.y), "r"(v.z), "r"(v.w) : "memory");
}
__device__ __forceinline__ void cpasync16(uint32_t dst, const void* src) {
    asm volatile("cp.async.cg.shared.global [%0], [%1], 16;" :: "r"(dst), "l"(src) : "memory");
}
#define CP_COMMIT() asm volatile("cp.async.commit_group;" ::: "memory")
#define CP_WAIT0()  asm volatile("cp.async.wait_group 0;"  ::: "memory")
__device__ __forceinline__ void prefetch_l2(const void* p) {
    asm volatile("prefetch.global.L2 [%0];" :: "l"(p));
}
__device__ __forceinline__ void stg_cs(float4* p, float4 v) {
    asm volatile("st.global.cs.v4.f32 [%0], {%1,%2,%3,%4};"
                 :: "l"(p), "f"(v.x), "f"(v.y), "f"(v.z), "f"(v.w) : "memory");
}
__device__ __forceinline__ unsigned enc_f(float f) {
    unsigned i = __float_as_uint(f);
    return (i & 0x80000000u) ? ~i : (i | 0x80000000u);
}
__device__ __forceinline__ float dec_f(unsigned u) {
    return __uint_as_float((u & 0x80000000u) ? (u & 0x7FFFFFFFu) : ~u);
}
#define RSWZ(row) (((uint32_t)((row) & 7)) << 4)

// ---------------- kernel A smem layout (512B rows, swizzled) ----------------
#define OFF_W    0u          // 256 rows x 512B = 131072
#define OFF_A    131072u     // 128 rows x 512B = 65536
#define OFF_BIAS 196608u     // 1024
#define OFF_SEG  197632u     // 512
#define SMEM_A_BYTES 198144

// ---------------- proj smem layout (tile M=32, double-buffered B/XA) ---------
#define P_OFF_B0   0u        // Wp chunk buf0: 32768
#define P_OFF_B1   32768u    // Wp chunk buf1: 32768
#define P_OFF_XA0  65536u    // xpool buf0: 4096
#define P_OFF_XA1  69632u    // xpool buf1: 4096
#define P_OFF_OUT  73728u    // 32 x 260 x 4 = 33280
#define P_OFF_CNT  107008u   // 128
#define P_OFF_INV  107136u   // 128
#define P_OFF_BP   107264u   // 1024
#define SMEM_P_BYTES 108288
#define OUT_LD 260

// ---------------- prep: init (4096 blocks, 1 uint4/thread) + wconv + rowstart
__global__ void prep_kernel(const float* __restrict__ W1,
                            const float* __restrict__ Wp,
                            const int*   __restrict__ bidx)
{
    const int b = blockIdx.x;
    const int t = threadIdx.x;

    if (b < 2048) {                       // zero g_seg_sum (2048*256 uint4)
        ((uint4*)g_seg_sum)[b * 256 + t] = make_uint4(0u, 0u, 0u, 0u);
    } else if (b < 4096) {                // zero g_seg_max
        ((uint4*)g_seg_max)[(b - 2048) * 256 + t] = make_uint4(0u, 0u, 0u, 0u);
    } else if (b < 4096 + 384) {          // wconv
        int i = (b - 4096) * 256 + t;
        if (i < 32768) {
            float2 f = ((const float2*)W1)[i];
            ((__half2*)g_W1h)[i] = __floats2half2_rn(f.x, f.y);
        } else {
            int j = i - 32768;
            float2 f = ((const float2*)Wp)[j];
            ((__half2*)g_Wph)[j] = __floats2half2_rn(f.x, f.y);
        }
    } else {                              // rowstart
        int s = (b - 4096 - 384) * 256 + t;
        int lo = 0, hi = N_ROWS;
        while (lo < hi) {
            int mid = (lo + hi) >> 1;
            if (__ldg(&bidx[mid]) < s) lo = mid + 1; else hi = mid;
        }
        g_rowstart[s] = lo;
        if (s == 0) g_rowstart[NSEG] = N_ROWS;
    }
}

// convert one batch of 8 float4 (fp32) to fp16 smem, batch b covers
// idx = b*2048 + j*256 + t over the 8192-float4 tile (row = idx>>6, q = idx&63)
__device__ __forceinline__ void cvt_store_batch(uint32_t sb, int bch, int t,
                                                const float4 pf[8]) {
#pragma unroll
    for (int j = 0; j < 8; j++) {
        int idx = bch * 2048 + j * 256 + t;
        int r = idx >> 6, q = idx & 63;
        __half2 h0 = __floats2half2_rn(pf[j].x, pf[j].y);
        __half2 h1 = __floats2half2_rn(pf[j].z, pf[j].w);
        uint32_t addr = (sb + OFF_A + (uint32_t)r * 512u + (uint32_t)q * 8u) ^ RSWZ(r);
        sts8(addr, *(uint32_t*)&h0, *(uint32_t*)&h1);
    }
}

// ---------------- kernel A: HMMA GEMM + shuffle segmented reduce -------------
// 8 warps 2Mx4N, warp tile 64x64, L2-prefetched next tile, batch-pipelined
// fp32->fp16 conversion; ks loop unrolled x4.
__global__ void __launch_bounds__(256, 1) gemm_pool_mma(
    const float* __restrict__ x,
    const int*   __restrict__ bidx,
    const float* __restrict__ b1)
{
    extern __shared__ char smem[];
    const uint32_t sb = smem_u32(smem);
    const int t    = threadIdx.x;
    const int w    = t >> 5;
    const int lane = t & 31;
    const int wm   = w >> 2;
    const int wn   = w & 3;

    float* bias_s = (float*)(smem + OFF_BIAS);
    int*   seg_s  = (int*)(smem + OFF_SEG);

    bias_s[t] = b1[t];

    {
        const int rowbase = blockIdx.x * 128;
        const float4* xb4 = (const float4*)(x + (size_t)rowbase * DIM);
        float4 pf[8];
#pragma unroll
        for (int j = 0; j < 8; j++) pf[j] = xb4[j * 256 + t];
#pragma unroll
        for (int bch = 0; bch < 4; bch++) {
            float4 nx[8];
            if (bch < 3) {
#pragma unroll
                for (int j = 0; j < 8; j++) nx[j] = xb4[(bch + 1) * 2048 + j * 256 + t];
            }
            cvt_store_batch(sb, bch, t, pf);
            if (bch < 3) {
#pragma unroll
                for (int j = 0; j < 8; j++) pf[j] = nx[j];
            }
        }
        if (t < 128) seg_s[t] = bidx[rowbase + t];
    }

    {
        const uint4* wsrc = (const uint4*)g_W1h;
#pragma unroll
        for (int j = 0; j < 32; j++) {
            int idx = j * 256 + t;
            int row = idx >> 5, q = idx & 31;
            uint32_t addr = (sb + OFF_W + (uint32_t)row * 512u + (uint32_t)q * 16u) ^ RSWZ(row);
            sts16(addr, wsrc[idx]);
        }
    }
    __syncthreads();

    const uint32_t xmask  = RSWZ(lane);
    const uint32_t a_base = sb + OFF_A + (uint32_t)(wm * 64 + (lane & 15)) * 512u + (uint32_t)(lane >> 4) * 16u;
    const uint32_t b_base = sb + OFF_W + (uint32_t)(wn * 64 + (lane & 15)) * 512u + (uint32_t)(lane >> 4) * 16u;
    const int colbase = wn * 64 + 2 * (lane & 3);

    for (int tile = blockIdx.x; tile < M_TILES; tile += GRID_A) {
        const int  ntile = tile + GRID_A;
        const bool more  = ntile < M_TILES;
        const float4* xn4 = (const float4*)(x + (size_t)ntile * 128 * DIM);

        if (more) {
            const char* pb = (const char*)xn4;
#pragma unroll
            for (int i = 0; i < 4; i++)
                prefetch_l2(pb + (size_t)(i * 256 + t) * 128);
        }

        float acc[4][8][4];
#pragma unroll
        for (int mi = 0; mi < 4; mi++)
#pragma unroll
            for (int ni = 0; ni < 8; ni++)
#pragma unroll
                for (int d = 0; d < 4; d++) acc[mi][ni][d] = 0.0f;

#pragma unroll 4
        for (int ks = 0; ks < 16; ks++) {
            const uint32_t koff = (uint32_t)ks * 32u;
            uint32_t af[4][4];
#pragma unroll
            for (int mi = 0; mi < 4; mi++)
                ldmat_x4(af[mi], (a_base + (uint32_t)mi * 8192u + koff) ^ xmask);
#pragma unroll
            for (int p = 0; p < 4; p++) {
                uint32_t bf[4];
                ldmat_x4(bf, (b_base + (uint32_t)p * 8192u + koff) ^ xmask);
#pragma unroll
                for (int mi = 0; mi < 4; mi++) {
                    mma16816(acc[mi][2 * p],     af[mi], bf[0], bf[2]);
                    mma16816(acc[mi][2 * p + 1], af[mi], bf[1], bf[3]);
                }
            }
        }
        __syncthreads();

        float4 pf[8];
        int segnext = 0;
        if (more) {
#pragma unroll
            for (int j = 0; j < 8; j++) pf[j] = xn4[j * 256 + t];
            if (t < 128) segnext = bidx[ntile * 128 + t];
        }

        {
            float bb[16];
#pragma unroll
            for (int i = 0; i < 16; i++) bb[i] = bias_s[colbase + (i >> 1) * 8 + (i & 1)];
#pragma unroll
            for (int mi = 0; mi < 4; mi++)
#pragma unroll
                for (int ni = 0; ni < 8; ni++)
#pragma unroll
                    for (int d = 0; d < 4; d++)
                        acc[mi][ni][d] += bb[ni * 2 + (d & 1)];

            float ps[16], pm[16];
            int pseg = -1;

#pragma unroll
            for (int b = 0; b < 8; b++) {
                const int mi = b >> 1, rh = b & 1;
                const int rb = wm * 64 + mi * 16 + rh * 8;
                const int seg0 = seg_s[rb];
                const int seg7 = seg_s[rb + 7];

                float v[16];
#pragma unroll
                for (int ni = 0; ni < 8; ni++) {
                    v[ni * 2]     = acc[mi][ni][2 * rh];
                    v[ni * 2 + 1] = acc[mi][ni][2 * rh + 1];
                }

                if (seg0 == seg7) {
                    if (pseg == seg0) {
#pragma unroll
                        for (int i = 0; i < 16; i++) {
                            ps[i] += v[i];
                            pm[i] = fmaxf(pm[i], v[i]);
                        }
                    } else {
                        if (pseg >= 0) {
#pragma unroll
                            for (int r = 4; r <= 16; r <<= 1)
#pragma unroll
                                for (int i = 0; i < 16; i++) {
                                    ps[i] += __shfl_xor_sync(0xFFFFFFFFu, ps[i], r);
                                    pm[i] = fmaxf(pm[i], __shfl_xor_sync(0xFFFFFFFFu, pm[i], r));
                                }
                            unsigned gb = (unsigned)pseg * DIM + colbase;
                            if (lane < 4) {
#pragma unroll
                                for (int i = 0; i < 16; i++)
                                    atomicAdd(&g_seg_sum[gb + (i >> 1) * 8 + (i & 1)], ps[i]);
                            } else if (lane < 8) {
#pragma unroll
                                for (int i = 0; i < 16; i++)
                                    atomicMax(&g_seg_max[gb + (i >> 1) * 8 + (i & 1)], enc_f(pm[i]));
                            }
                        }
#pragma unroll
                        for (int i = 0; i < 16; i++) { ps[i] = v[i]; pm[i] = v[i]; }
                        pseg = seg0;
                    }
                } else {
                    const int myseg = seg_s[rb + (lane >> 2)];
                    unsigned gb = (unsigned)myseg * DIM + colbase;
#pragma unroll
                    for (int i = 0; i < 16; i++) {
                        atomicAdd(&g_seg_sum[gb + (i >> 1) * 8 + (i & 1)], v[i]);
                        atomicMax(&g_seg_max[gb + (i >> 1) * 8 + (i & 1)], enc_f(v[i]));
                    }
                }
            }
            if (pseg >= 0) {
#pragma unroll
                for (int r = 4; r <= 16; r <<= 1)
#pragma unroll
                    for (int i = 0; i < 16; i++) {
                        ps[i] += __shfl_xor_sync(0xFFFFFFFFu, ps[i], r);
                        pm[i] = fmaxf(pm[i], __shfl_xor_sync(0xFFFFFFFFu, pm[i], r));
                    }
                unsigned gb = (unsigned)pseg * DIM + colbase;
                if (lane < 4) {
#pragma unroll
                    for (int i = 0; i < 16; i++)
                        atomicAdd(&g_seg_sum[gb + (i >> 1) * 8 + (i & 1)], ps[i]);
                } else if (lane < 8) {
#pragma unroll
                    for (int i = 0; i < 16; i++)
                        atomicMax(&g_seg_max[gb + (i >> 1) * 8 + (i & 1)], enc_f(pm[i]));
                }
            }
        }

        if (more) {
#pragma unroll
            for (int bch = 0; bch < 4; bch++) {
                float4 nx[8];
                if (bch < 3) {
#pragma unroll
                    for (int j = 0; j < 8; j++) nx[j] = xn4[(bch + 1) * 2048 + j * 256 + t];
                }
                cvt_store_batch(sb, bch, t, pf);
                if (bch < 3) {
#pragma unroll
                    for (int j = 0; j < 8; j++) pf[j] = nx[j];
                }
            }
        }
        __syncthreads();
        if (more && t < 128) seg_s[t] = segnext;
    }
}

// issue cp.async for Wp chunk kc into buffer buf (2048 16B chunks / 256 thr)
__device__ __forceinline__ void issue_wp(uint32_t sb, int kc, int buf, int t) {
    const uint32_t base = sb + (buf ? P_OFF_B1 : P_OFF_B0);
#pragma unroll
    for (int i = 0; i < 8; i++) {
        int idx = i * 256 + t;
        int row = idx >> 3, q = idx & 7;
        uint32_t dst = (base + (uint32_t)row * 128u + (uint32_t)q * 16u) ^ RSWZ(row);
        cpasync16(dst, g_Wph + (size_t)row * 512 + kc * 64 + q * 8);
    }
}

// ---------------- proj: HMMA fp16 GEMM (cp.async double-buffered Wp) ---------
__global__ void __launch_bounds__(256, 2) proj_scatter(
    const int*   __restrict__ bidx,
    const float* __restrict__ bp,
    float4*      __restrict__ out4)
{
    extern __shared__ char smem[];
    const uint32_t sb = smem_u32(smem);
    const int t    = threadIdx.x;
    const int w    = t >> 5;
    const int lane = t & 31;
    const int wn   = w;
    const int tileM = blockIdx.x * 32;

    int*   cnt_s  = (int*)(smem + P_OFF_CNT);
    float* invc_s = (float*)(smem + P_OFF_INV);
    float* bp_s   = (float*)(smem + P_OFF_BP);
    float* outs   = (float*)(smem + P_OFF_OUT);

    if (t < 32) {
        int cn = g_rowstart[tileM + t + 1] - g_rowstart[tileM + t];
        cnt_s[t]  = cn;
        invc_s[t] = 1.0f / (float)max(cn, 1);
    }
    bp_s[t] = bp[t];

    issue_wp(sb, 0, 0, t);
    CP_COMMIT();
    __syncthreads();

    const uint32_t xmask   = RSWZ(lane);
    const uint32_t a_base0 = sb + P_OFF_XA0 + (uint32_t)(lane & 15) * 128u + (uint32_t)(lane >> 4) * 16u;
    const uint32_t b_base0 = sb + P_OFF_B0  + (uint32_t)(wn * 32 + (lane & 15)) * 128u + (uint32_t)(lane >> 4) * 16u;

    float acc[2][4][4];
#pragma unroll
    for (int mi = 0; mi < 2; mi++)
#pragma unroll
        for (int ni = 0; ni < 4; ni++)
#pragma unroll
            for (int d = 0; d < 4; d++) acc[mi][ni][d] = 0.0f;

#pragma unroll 1
    for (int kc = 0; kc < 8; kc++) {
        const int bf_sel = kc & 1;
        const uint32_t xa_dst = sb + (bf_sel ? P_OFF_XA1 : P_OFF_XA0);

#pragma unroll
        for (int i = 0; i < 2; i++) {
            int idx = i * 256 + t;
            int row = idx >> 4, q = idx & 15;
            float4 va;
            if (kc < 4) {
                va = *(const float4*)&g_seg_sum[(size_t)(tileM + row) * DIM + kc * 64 + q * 4];
                float iv = invc_s[row];
                va.x *= iv; va.y *= iv; va.z *= iv; va.w *= iv;
            } else {
                uint4 u = *(const uint4*)&g_seg_max[(size_t)(tileM + row) * DIM + (kc - 4) * 64 + q * 4];
                if (cnt_s[row] > 0) {
                    va.x = dec_f(u.x); va.y = dec_f(u.y); va.z = dec_f(u.z); va.w = dec_f(u.w);
                } else {
                    va.x = va.y = va.z = va.w = 0.0f;
                }
            }
            __half2 h0 = __floats2half2_rn(va.x, va.y);
            __half2 h1 = __floats2half2_rn(va.z, va.w);
            uint32_t addr = (xa_dst + (uint32_t)row * 128u + (uint32_t)q * 8u) ^ RSWZ(row);
            sts8(addr, *(uint32_t*)&h0, *(uint32_t*)&h1);
        }

        CP_WAIT0();
        __syncthreads();

        if (kc < 7) {
            issue_wp(sb, kc + 1, (kc + 1) & 1, t);
            CP_COMMIT();
        }

        const uint32_t a_base = a_base0 + (uint32_t)bf_sel * 4096u;
        const uint32_t b_base = b_base0 + (uint32_t)bf_sel * 32768u;
#pragma unroll
        for (int ks = 0; ks < 4; ks++) {
            const uint32_t koff = (uint32_t)ks * 32u;
            uint32_t a0[4], a1[4];
            ldmat_x4(a0, (a_base + koff) ^ xmask);
            ldmat_x4(a1, (a_base + 16u * 128u + koff) ^ xmask);
#pragma unroll
            for (int p = 0; p < 2; p++) {
                uint32_t bfr[4];
                ldmat_x4(bfr, (b_base + (uint32_t)p * 2048u + koff) ^ xmask);
                mma16816(acc[0][2 * p],     a0, bfr[0], bfr[2]);
                mma16816(acc[0][2 * p + 1], a0, bfr[1], bfr[3]);
                mma16816(acc[1][2 * p],     a1, bfr[0], bfr[2]);
                mma16816(acc[1][2 * p + 1], a1, bfr[1], bfr[3]);
            }
        }
    }

    {
        const int r0 = lane >> 2;
        const int c0 = wn * 32 + 2 * (lane & 3);
#pragma unroll
        for (int mi = 0; mi < 2; mi++)
#pragma unroll
            for (int ni = 0; ni < 4; ni++) {
                int col = c0 + ni * 8;
                float bb0 = bp_s[col], bb1 = bp_s[col + 1];
                int rr = r0 + mi * 16;
                outs[rr * OUT_LD + col]           = acc[mi][ni][0] + bb0;
                outs[rr * OUT_LD + col + 1]       = acc[mi][ni][1] + bb1;
                outs[(rr + 8) * OUT_LD + col]     = acc[mi][ni][2] + bb0;
                outs[(rr + 8) * OUT_LD + col + 1] = acc[mi][ni][3] + bb1;
            }
    }
    __syncthreads();

    // ---- scatter rows [rowstart(tileM), rowstart(tileM+32)), streaming ----
    const int rstart = g_rowstart[tileM];
    const int rend   = g_rowstart[tileM + 32];
    const int cq     = t & 63;
    int r = rstart + (t >> 6);
    for (; r + 12 < rend; r += 16) {
        int s0 = __ldg(&bidx[r])      - tileM;
        int s1 = __ldg(&bidx[r +  4]) - tileM;
        int s2 = __ldg(&bidx[r +  8]) - tileM;
        int s3 = __ldg(&bidx[r + 12]) - tileM;
        float4 v0 = *(const float4*)&outs[s0 * OUT_LD + cq * 4];
        float4 v1 = *(const float4*)&outs[s1 * OUT_LD + cq * 4];
        float4 v2 = *(const float4*)&outs[s2 * OUT_LD + cq * 4];
        float4 v3 = *(const float4*)&outs[s3 * OUT_LD + cq * 4];
        stg_cs(&out4[(size_t)r * 64 + cq],        v0);
        stg_cs(&out4[(size_t)(r +  4) * 64 + cq], v1);
        stg_cs(&out4[(size_t)(r +  8) * 64 + cq], v2);
        stg_cs(&out4[(size_t)(r + 12) * 64 + cq], v3);
    }
    for (; r < rend; r += 4) {
        int s0 = __ldg(&bidx[r]) - tileM;
        stg_cs(&out4[(size_t)r * 64 + cq], *(const float4*)&outs[s0 * OUT_LD + cq * 4]);
    }
}

// ---------------- launch -----------------------------------------------------
extern "C" void kernel_launch(void* const* d_in, const int* in_sizes, int n_in,
                              void* d_out, int out_size) {
    const float* x    = (const float*)d_in[0];
    const int*   bidx = (const int*)  d_in[1];
    const float* W1   = (const float*)d_in[2];
    const float* b1   = (const float*)d_in[3];
    const float* Wp   = (const float*)d_in[4];
    const float* bp   = (const float*)d_in[5];

    cudaFuncSetAttribute(gemm_pool_mma, cudaFuncAttributeMaxDynamicSharedMemorySize,
                         SMEM_A_BYTES);
    cudaFuncSetAttribute(proj_scatter, cudaFuncAttributeMaxDynamicSharedMemorySize,
                         SMEM_P_BYTES);

    prep_kernel<<<4096 + 384 + 32, 256>>>(W1, Wp, bidx);

    gemm_pool_mma<<<GRID_A, 256, SMEM_A_BYTES>>>(x, bidx, b1);

    proj_scatter<<<NSEG / 32, 256, SMEM_P_BYTES>>>(bidx, bp, (float4*)d_out);
}

// round 17
// speedup vs baseline: 1.2805x; 1.0080x over previous
#include <cuda_runtime.h>
#include <cuda_fp16.h>
#include <cstdint>

#define N_ROWS 524288
#define DIM 256
#define NSEG 8192
#define M_TILES 4096      // 128-row M tiles
#define GRID_A 148

// ---------------- scratch (device globals) ----------------------------------
__device__ float    g_seg_sum[NSEG * DIM];
__device__ unsigned g_seg_max[NSEG * DIM];
__device__ int      g_rowstart[NSEG + 1];
__device__ __half   g_W1h[DIM * DIM];
__device__ __half   g_Wph[DIM * 2 * DIM];

// ---------------- helpers ----------------------------------------------------
__device__ __forceinline__ uint32_t smem_u32(const void* p) {
    uint32_t a;
    asm("{ .reg .u64 t; cvta.to.shared.u64 t, %1; cvt.u32.u64 %0, t; }" : "=r"(a) : "l"(p));
    return a;
}
__device__ __forceinline__ void ldmat_x4(uint32_t r[4], uint32_t addr) {
    asm volatile("ldmatrix.sync.aligned.m8n8.x4.shared.b16 {%0,%1,%2,%3}, [%4];"
                 : "=r"(r[0]), "=r"(r[1]), "=r"(r[2]), "=r"(r[3]) : "r"(addr));
}
__device__ __forceinline__ void mma16816(float d[4], const uint32_t a[4],
                                         uint32_t b0, uint32_t b1) {
    asm volatile("mma.sync.aligned.m16n8k16.row.col.f32.f16.f16.f32 "
                 "{%0,%1,%2,%3}, {%4,%5,%6,%7}, {%8,%9}, {%0,%1,%2,%3};"
                 : "+f"(d[0]), "+f"(d[1]), "+f"(d[2]), "+f"(d[3])
                 : "r"(a[0]), "r"(a[1]), "r"(a[2]), "r"(a[3]), "r"(b0), "r"(b1));
}
__device__ __forceinline__ void sts8(uint32_t addr, uint32_t u0, uint32_t u1) {
    asm volatile("st.shared.v2.b32 [%0], {%1,%2};" :: "r"(addr), "r"(u0), "r"(u1) : "memory");
}
__device__ __forceinline__ void sts16(uint32_t addr, uint4 v) {
    asm volatile("st.shared.v4.b32 [%0], {%1,%2,%3,%4};"
                 :: "r"(addr), "r"(v.x), "r"(v.y), "r"(v.z), "r"(v.w) : "memory");
}
__device__ __forceinline__ void cpasync16(uint32_t dst, const void* src) {
    asm volatile("cp.async.cg.shared.global [%0], [%1], 16;" :: "r"(dst), "l"(src) : "memory");
}
#define CP_COMMIT() asm volatile("cp.async.commit_group;" ::: "memory")
#define CP_WAIT0()  asm volatile("cp.async.wait_group 0;"  ::: "memory")
__device__ __forceinline__ void prefetch_l2(const void* p) {
    asm volatile("prefetch.global.L2 [%0];" :: "l"(p));
}
__device__ __forceinline__ void stg_cs(float4* p, float4 v) {
    asm volatile("st.global.cs.v4.f32 [%0], {%1,%2,%3,%4};"
                 :: "l"(p), "f"(v.x), "f"(v.y), "f"(v.z), "f"(v.w) : "memory");
}
__device__ __forceinline__ unsigned enc_f(float f) {
    unsigned i = __float_as_uint(f);
    return (i & 0x80000000u) ? ~i : (i | 0x80000000u);
}
__device__ __forceinline__ float dec_f(unsigned u) {
    return __uint_as_float((u & 0x80000000u) ? (u & 0x7FFFFFFFu) : ~u);
}
#define RSWZ(row) (((uint32_t)((row) & 7)) << 4)

// ---------------- kernel A smem layout (512B rows, swizzled) ----------------
#define OFF_W    0u          // 256 rows x 512B = 131072
#define OFF_A    131072u     // 128 rows x 512B = 65536
#define OFF_BIAS 196608u     // 1024
#define OFF_SEG  197632u     // 512
#define SMEM_A_BYTES 198144

// ---------------- proj smem layout (tile M=32, double-buffered B/XA) ---------
#define P_OFF_B0   0u        // Wp chunk buf0: 32768
#define P_OFF_B1   32768u    // Wp chunk buf1: 32768
#define P_OFF_XA0  65536u    // xpool buf0: 4096
#define P_OFF_XA1  69632u    // xpool buf1: 4096
#define P_OFF_OUT  73728u    // 32 x 260 x 4 = 33280
#define P_OFF_CNT  107008u   // 128
#define P_OFF_INV  107136u   // 128
#define P_OFF_BP   107264u   // 1024
#define SMEM_P_BYTES 108288
#define OUT_LD 260

// ---------------- prep: init + wconv + rowstart (role blocks) ----------------
__global__ void prep_kernel(const float* __restrict__ W1,
                            const float* __restrict__ Wp,
                            const int*   __restrict__ bidx)
{
    const int b = blockIdx.x;
    const int t = threadIdx.x;

    if (b < 2048) {                       // zero g_seg_sum (2048*256 uint4)
        ((uint4*)g_seg_sum)[b * 256 + t] = make_uint4(0u, 0u, 0u, 0u);
    } else if (b < 4096) {                // zero g_seg_max
        ((uint4*)g_seg_max)[(b - 2048) * 256 + t] = make_uint4(0u, 0u, 0u, 0u);
    } else if (b < 4096 + 384) {          // wconv
        int i = (b - 4096) * 256 + t;
        if (i < 32768) {
            float2 f = ((const float2*)W1)[i];
            ((__half2*)g_W1h)[i] = __floats2half2_rn(f.x, f.y);
        } else {
            int j = i - 32768;
            float2 f = ((const float2*)Wp)[j];
            ((__half2*)g_Wph)[j] = __floats2half2_rn(f.x, f.y);
        }
    } else {                              // rowstart
        int s = (b - 4096 - 384) * 256 + t;
        int lo = 0, hi = N_ROWS;
        while (lo < hi) {
            int mid = (lo + hi) >> 1;
            if (__ldg(&bidx[mid]) < s) lo = mid + 1; else hi = mid;
        }
        g_rowstart[s] = lo;
        if (s == 0) g_rowstart[NSEG] = N_ROWS;
    }
}

// convert one batch of 8 float4 (fp32) to fp16 smem, batch b covers
// idx = b*2048 + j*256 + t over the 8192-float4 tile (row = idx>>6, q = idx&63)
__device__ __forceinline__ void cvt_store_batch(uint32_t sb, int bch, int t,
                                                const float4 pf[8]) {
#pragma unroll
    for (int j = 0; j < 8; j++) {
        int idx = bch * 2048 + j * 256 + t;
        int r = idx >> 6, q = idx & 63;
        __half2 h0 = __floats2half2_rn(pf[j].x, pf[j].y);
        __half2 h1 = __floats2half2_rn(pf[j].z, pf[j].w);
        uint32_t addr = (sb + OFF_A + (uint32_t)r * 512u + (uint32_t)q * 8u) ^ RSWZ(r);
        sts8(addr, *(uint32_t*)&h0, *(uint32_t*)&h1);
    }
}

// ---------------- kernel A: HMMA GEMM + shuffle segmented reduce -------------
// 8 warps 2Mx4N, warp tile 64x64; L2-prefetch next tile; flat-MLP conversion
// (batch0 behind epilogue, batches 1-3 loaded together after acc dies).
__global__ void __launch_bounds__(256, 1) gemm_pool_mma(
    const float* __restrict__ x,
    const int*   __restrict__ bidx,
    const float* __restrict__ b1)
{
    extern __shared__ char smem[];
    const uint32_t sb = smem_u32(smem);
    const int t    = threadIdx.x;
    const int w    = t >> 5;
    const int lane = t & 31;
    const int wm   = w >> 2;
    const int wn   = w & 3;

    float* bias_s = (float*)(smem + OFF_BIAS);
    int*   seg_s  = (int*)(smem + OFF_SEG);

    bias_s[t] = b1[t];

    // ---- first tile: batch0 regs, then batches 1-3 flat, convert all ----
    {
        const int rowbase = blockIdx.x * 128;
        const float4* xb4 = (const float4*)(x + (size_t)rowbase * DIM);
        float4 pf[8], nx[24];
#pragma unroll
        for (int j = 0; j < 8; j++) pf[j] = xb4[j * 256 + t];
#pragma unroll
        for (int j = 0; j < 24; j++) nx[j] = xb4[2048 + j * 256 + t];
        cvt_store_batch(sb, 0, t, pf);
#pragma unroll
        for (int bch = 1; bch < 4; bch++)
            cvt_store_batch(sb, bch, t, &nx[(bch - 1) * 8]);
        if (t < 128) seg_s[t] = bidx[rowbase + t];
    }

    // ---- W1 fp16 -> SMEM [n][k] 512B rows, swizzled (once per CTA) ----
    {
        const uint4* wsrc = (const uint4*)g_W1h;
#pragma unroll
        for (int j = 0; j < 32; j++) {
            int idx = j * 256 + t;
            int row = idx >> 5, q = idx & 31;
            uint32_t addr = (sb + OFF_W + (uint32_t)row * 512u + (uint32_t)q * 16u) ^ RSWZ(row);
            sts16(addr, wsrc[idx]);
        }
    }
    __syncthreads();

    const uint32_t xmask  = RSWZ(lane);
    const uint32_t a_base = sb + OFF_A + (uint32_t)(wm * 64 + (lane & 15)) * 512u + (uint32_t)(lane >> 4) * 16u;
    const uint32_t b_base = sb + OFF_W + (uint32_t)(wn * 64 + (lane & 15)) * 512u + (uint32_t)(lane >> 4) * 16u;
    const int colbase = wn * 64 + 2 * (lane & 3);

    for (int tile = blockIdx.x; tile < M_TILES; tile += GRID_A) {
        const int  ntile = tile + GRID_A;
        const bool more  = ntile < M_TILES;
        const float4* xn4 = (const float4*)(x + (size_t)ntile * 128 * DIM);

        if (more) {
            const char* pb = (const char*)xn4;
#pragma unroll
            for (int i = 0; i < 4; i++)
                prefetch_l2(pb + (size_t)(i * 256 + t) * 128);
        }

        float acc[4][8][4];
#pragma unroll
        for (int mi = 0; mi < 4; mi++)
#pragma unroll
            for (int ni = 0; ni < 8; ni++)
#pragma unroll
                for (int d = 0; d < 4; d++) acc[mi][ni][d] = 0.0f;

#pragma unroll 4
        for (int ks = 0; ks < 16; ks++) {
            const uint32_t koff = (uint32_t)ks * 32u;
            uint32_t af[4][4];
#pragma unroll
            for (int mi = 0; mi < 4; mi++)
                ldmat_x4(af[mi], (a_base + (uint32_t)mi * 8192u + koff) ^ xmask);
#pragma unroll
            for (int p = 0; p < 4; p++) {
                uint32_t bf[4];
                ldmat_x4(bf, (b_base + (uint32_t)p * 8192u + koff) ^ xmask);
#pragma unroll
                for (int mi = 0; mi < 4; mi++) {
                    mma16816(acc[mi][2 * p],     af[mi], bf[0], bf[2]);
                    mma16816(acc[mi][2 * p + 1], af[mi], bf[1], bf[3]);
                }
            }
        }
        __syncthreads();

        // ---- prefetch batch0 of next tile (hidden behind epilogue) ----
        float4 pf[8];
        int segnext = 0;
        if (more) {
#pragma unroll
            for (int j = 0; j < 8; j++) pf[j] = xn4[j * 256 + t];
            if (t < 128) segnext = bidx[ntile * 128 + t];
        }

        // ---- barrier-free epilogue: bias + shuffle segmented reduce ----
        {
            float bb[16];
#pragma unroll
            for (int i = 0; i < 16; i++) bb[i] = bias_s[colbase + (i >> 1) * 8 + (i & 1)];
#pragma unroll
            for (int mi = 0; mi < 4; mi++)
#pragma unroll
                for (int ni = 0; ni < 8; ni++)
#pragma unroll
                    for (int d = 0; d < 4; d++)
                        acc[mi][ni][d] += bb[ni * 2 + (d & 1)];

            float ps[16], pm[16];
            int pseg = -1;

#pragma unroll
            for (int b = 0; b < 8; b++) {
                const int mi = b >> 1, rh = b & 1;
                const int rb = wm * 64 + mi * 16 + rh * 8;
                const int seg0 = seg_s[rb];
                const int seg7 = seg_s[rb + 7];

                float v[16];
#pragma unroll
                for (int ni = 0; ni < 8; ni++) {
                    v[ni * 2]     = acc[mi][ni][2 * rh];
                    v[ni * 2 + 1] = acc[mi][ni][2 * rh + 1];
                }

                if (seg0 == seg7) {
                    if (pseg == seg0) {
#pragma unroll
                        for (int i = 0; i < 16; i++) {
                            ps[i] += v[i];
                            pm[i] = fmaxf(pm[i], v[i]);
                        }
                    } else {
                        if (pseg >= 0) {
#pragma unroll
                            for (int r = 4; r <= 16; r <<= 1)
#pragma unroll
                                for (int i = 0; i < 16; i++) {
                                    ps[i] += __shfl_xor_sync(0xFFFFFFFFu, ps[i], r);
                                    pm[i] = fmaxf(pm[i], __shfl_xor_sync(0xFFFFFFFFu, pm[i], r));
                                }
                            unsigned gb = (unsigned)pseg * DIM + colbase;
                            if (lane < 4) {
#pragma unroll
                                for (int i = 0; i < 16; i++)
                                    atomicAdd(&g_seg_sum[gb + (i >> 1) * 8 + (i & 1)], ps[i]);
                            } else if (lane < 8) {
#pragma unroll
                                for (int i = 0; i < 16; i++)
                                    atomicMax(&g_seg_max[gb + (i >> 1) * 8 + (i & 1)], enc_f(pm[i]));
                            }
                        }
#pragma unroll
                        for (int i = 0; i < 16; i++) { ps[i] = v[i]; pm[i] = v[i]; }
                        pseg = seg0;
                    }
                } else {
                    const int myseg = seg_s[rb + (lane >> 2)];
                    unsigned gb = (unsigned)myseg * DIM + colbase;
#pragma unroll
                    for (int i = 0; i < 16; i++) {
                        atomicAdd(&g_seg_sum[gb + (i >> 1) * 8 + (i & 1)], v[i]);
                        atomicMax(&g_seg_max[gb + (i >> 1) * 8 + (i & 1)], enc_f(v[i]));
                    }
                }
            }
            if (pseg >= 0) {
#pragma unroll
                for (int r = 4; r <= 16; r <<= 1)
#pragma unroll
                    for (int i = 0; i < 16; i++) {
                        ps[i] += __shfl_xor_sync(0xFFFFFFFFu, ps[i], r);
                        pm[i] = fmaxf(pm[i], __shfl_xor_sync(0xFFFFFFFFu, pm[i], r));
                    }
                unsigned gb = (unsigned)pseg * DIM + colbase;
                if (lane < 4) {
#pragma unroll
                    for (int i = 0; i < 16; i++)
                        atomicAdd(&g_seg_sum[gb + (i >> 1) * 8 + (i & 1)], ps[i]);
                } else if (lane < 8) {
#pragma unroll
                    for (int i = 0; i < 16; i++)
                        atomicMax(&g_seg_max[gb + (i >> 1) * 8 + (i & 1)], enc_f(pm[i]));
                }
            }
        }

        // ---- batches 1-3: flat MLP=24 load (acc dead), then convert all ----
        if (more) {
            float4 nx[24];
#pragma unroll
            for (int j = 0; j < 24; j++) nx[j] = xn4[2048 + j * 256 + t];
            cvt_store_batch(sb, 0, t, pf);
#pragma unroll
            for (int bch = 1; bch < 4; bch++)
                cvt_store_batch(sb, bch, t, &nx[(bch - 1) * 8]);
        }
        __syncthreads();
        if (more && t < 128) seg_s[t] = segnext;
    }
}

// issue cp.async for Wp chunk kc into buffer buf (2048 16B chunks / 256 thr)
__device__ __forceinline__ void issue_wp(uint32_t sb, int kc, int buf, int t) {
    const uint32_t base = sb + (buf ? P_OFF_B1 : P_OFF_B0);
#pragma unroll
    for (int i = 0; i < 8; i++) {
        int idx = i * 256 + t;
        int row = idx >> 3, q = idx & 7;
        uint32_t dst = (base + (uint32_t)row * 128u + (uint32_t)q * 16u) ^ RSWZ(row);
        cpasync16(dst, g_Wph + (size_t)row * 512 + kc * 64 + q * 8);
    }
}

// ---------------- proj: HMMA fp16 GEMM (cp.async double-buffered Wp) ---------
__global__ void __launch_bounds__(256, 2) proj_scatter(
    const int*   __restrict__ bidx,
    const float* __restrict__ bp,
    float4*      __restrict__ out4)
{
    extern __shared__ char smem[];
    const uint32_t sb = smem_u32(smem);
    const int t    = threadIdx.x;
    const int w    = t >> 5;
    const int lane = t & 31;
    const int wn   = w;
    const int tileM = blockIdx.x * 32;

    int*   cnt_s  = (int*)(smem + P_OFF_CNT);
    float* invc_s = (float*)(smem + P_OFF_INV);
    float* bp_s   = (float*)(smem + P_OFF_BP);
    float* outs   = (float*)(smem + P_OFF_OUT);

    if (t < 32) {
        int cn = g_rowstart[tileM + t + 1] - g_rowstart[tileM + t];
        cnt_s[t]  = cn;
        invc_s[t] = 1.0f / (float)max(cn, 1);
    }
    bp_s[t] = bp[t];

    issue_wp(sb, 0, 0, t);
    CP_COMMIT();
    __syncthreads();

    const uint32_t xmask   = RSWZ(lane);
    const uint32_t a_base0 = sb + P_OFF_XA0 + (uint32_t)(lane & 15) * 128u + (uint32_t)(lane >> 4) * 16u;
    const uint32_t b_base0 = sb + P_OFF_B0  + (uint32_t)(wn * 32 + (lane & 15)) * 128u + (uint32_t)(lane >> 4) * 16u;

    float acc[2][4][4];
#pragma unroll
    for (int mi = 0; mi < 2; mi++)
#pragma unroll
        for (int ni = 0; ni < 4; ni++)
#pragma unroll
            for (int d = 0; d < 4; d++) acc[mi][ni][d] = 0.0f;

#pragma unroll 1
    for (int kc = 0; kc < 8; kc++) {
        const int bf_sel = kc & 1;
        const uint32_t xa_dst = sb + (bf_sel ? P_OFF_XA1 : P_OFF_XA0);

#pragma unroll
        for (int i = 0; i < 2; i++) {
            int idx = i * 256 + t;
            int row = idx >> 4, q = idx & 15;
            float4 va;
            if (kc < 4) {
                va = *(const float4*)&g_seg_sum[(size_t)(tileM + row) * DIM + kc * 64 + q * 4];
                float iv = invc_s[row];
                va.x *= iv; va.y *= iv; va.z *= iv; va.w *= iv;
            } else {
                uint4 u = *(const uint4*)&g_seg_max[(size_t)(tileM + row) * DIM + (kc - 4) * 64 + q * 4];
                if (cnt_s[row] > 0) {
                    va.x = dec_f(u.x); va.y = dec_f(u.y); va.z = dec_f(u.z); va.w = dec_f(u.w);
                } else {
                    va.x = va.y = va.z = va.w = 0.0f;
                }
            }
            __half2 h0 = __floats2half2_rn(va.x, va.y);
            __half2 h1 = __floats2half2_rn(va.z, va.w);
            uint32_t addr = (xa_dst + (uint32_t)row * 128u + (uint32_t)q * 8u) ^ RSWZ(row);
            sts8(addr, *(uint32_t*)&h0, *(uint32_t*)&h1);
        }

        CP_WAIT0();
        __syncthreads();

        if (kc < 7) {
            issue_wp(sb, kc + 1, (kc + 1) & 1, t);
            CP_COMMIT();
        }

        const uint32_t a_base = a_base0 + (uint32_t)bf_sel * 4096u;
        const uint32_t b_base = b_base0 + (uint32_t)bf_sel * 32768u;
#pragma unroll
        for (int ks = 0; ks < 4; ks++) {
            const uint32_t koff = (uint32_t)ks * 32u;
            uint32_t a0[4], a1[4];
            ldmat_x4(a0, (a_base + koff) ^ xmask);
            ldmat_x4(a1, (a_base + 16u * 128u + koff) ^ xmask);
#pragma unroll
            for (int p = 0; p < 2; p++) {
                uint32_t bfr[4];
                ldmat_x4(bfr, (b_base + (uint32_t)p * 2048u + koff) ^ xmask);
                mma16816(acc[0][2 * p],     a0, bfr[0], bfr[2]);
                mma16816(acc[0][2 * p + 1], a0, bfr[1], bfr[3]);
                mma16816(acc[1][2 * p],     a1, bfr[0], bfr[2]);
                mma16816(acc[1][2 * p + 1], a1, bfr[1], bfr[3]);
            }
        }
    }

    {
        const int r0 = lane >> 2;
        const int c0 = wn * 32 + 2 * (lane & 3);
#pragma unroll
        for (int mi = 0; mi < 2; mi++)
#pragma unroll
            for (int ni = 0; ni < 4; ni++) {
                int col = c0 + ni * 8;
                float bb0 = bp_s[col], bb1 = bp_s[col + 1];
                int rr = r0 + mi * 16;
                outs[rr * OUT_LD + col]           = acc[mi][ni][0] + bb0;
                outs[rr * OUT_LD + col + 1]       = acc[mi][ni][1] + bb1;
                outs[(rr + 8) * OUT_LD + col]     = acc[mi][ni][2] + bb0;
                outs[(rr + 8) * OUT_LD + col + 1] = acc[mi][ni][3] + bb1;
            }
    }
    __syncthreads();

    // ---- scatter rows [rowstart(tileM), rowstart(tileM+32)), streaming ----
    const int rstart = g_rowstart[tileM];
    const int rend   = g_rowstart[tileM + 32];
    const int cq     = t & 63;
    int r = rstart + (t >> 6);
    for (; r + 12 < rend; r += 16) {
        int s0 = __ldg(&bidx[r])      - tileM;
        int s1 = __ldg(&bidx[r +  4]) - tileM;
        int s2 = __ldg(&bidx[r +  8]) - tileM;
        int s3 = __ldg(&bidx[r + 12]) - tileM;
        float4 v0 = *(const float4*)&outs[s0 * OUT_LD + cq * 4];
        float4 v1 = *(const float4*)&outs[s1 * OUT_LD + cq * 4];
        float4 v2 = *(const float4*)&outs[s2 * OUT_LD + cq * 4];
        float4 v3 = *(const float4*)&outs[s3 * OUT_LD + cq * 4];
        stg_cs(&out4[(size_t)r * 64 + cq],        v0);
        stg_cs(&out4[(size_t)(r +  4) * 64 + cq], v1);
        stg_cs(&out4[(size_t)(r +  8) * 64 + cq], v2);
        stg_cs(&out4[(size_t)(r + 12) * 64 + cq], v3);
    }
    for (; r < rend; r += 4) {
        int s0 = __ldg(&bidx[r]) - tileM;
        stg_cs(&out4[(size_t)r * 64 + cq], *(const float4*)&outs[s0 * OUT_LD + cq * 4]);
    }
}

// ---------------- launch -----------------------------------------------------
extern "C" void kernel_launch(void* const* d_in, const int* in_sizes, int n_in,
                              void* d_out, int out_size) {
    const float* x    = (const float*)d_in[0];
    const int*   bidx = (const int*)  d_in[1];
    const float* W1   = (const float*)d_in[2];
    const float* b1   = (const float*)d_in[3];
    const float* Wp   = (const float*)d_in[4];
    const float* bp   = (const float*)d_in[5];

    cudaFuncSetAttribute(gemm_pool_mma, cudaFuncAttributeMaxDynamicSharedMemorySize,
                         SMEM_A_BYTES);
    cudaFuncSetAttribute(proj_scatter, cudaFuncAttributeMaxDynamicSharedMemorySize,
                         SMEM_P_BYTES);

    prep_kernel<<<4096 + 384 + 32, 256>>>(W1, Wp, bidx);

    gemm_pool_mma<<<GRID_A, 256, SMEM_A_BYTES>>>(x, bidx, b1);

    proj_scatter<<<NSEG / 32, 256, SMEM_P_BYTES>>>(bidx, bp, (float4*)d_out);
}